// round 9
// baseline (speedup 1.0000x reference)
#include <cuda_runtime.h>
#include <math.h>

#define NB 2
#define SN 512
#define DIM 256
#define NH 8
#define HD 32
#define QSCALE 0.17677669529663689f   // 1/sqrt(32)
#define FREQC  0.5756462732485115f    // ln(10000)/16

// ---------------- scratch (device globals) ----------------
__device__ __align__(256) float g_dist [NB*SN*SN];
__device__ __align__(256) float g_nodes[NB*SN*DIM];
__device__ __align__(256) float g_h    [NB*SN*DIM];
__device__ __align__(256) float g_qkv  [NB*SN*3*DIM];
__device__ __align__(256) float g_q    [NB*NH*SN*HD];
__device__ __align__(256) float g_kt   [NB*NH*HD*SN];
__device__ __align__(256) float g_v    [NB*NH*SN*HD];
__device__ __align__(256) float g_qwe  [NB*NH*SN];
__device__ __align__(256) float g_qbe  [NB*NH*SN];
__device__ __align__(256) float g_attno[NB*SN*DIM];
__device__ __align__(256) float g_out  [NB*SN*DIM];
__device__ __align__(256) float g_tab  [SN*32];
__device__ __align__(256) float g_wq   [2*DIM*DIM];
__device__ __align__(256) float g_wkv  [2*DIM*2*DIM];
__device__ __align__(256) float g_wo   [2*DIM*DIM];

// ---------------- helpers ----------------
__device__ __forceinline__ float warpSum(float v){
    #pragma unroll
    for(int o=16;o;o>>=1) v += __shfl_xor_sync(0xffffffffu, v, o);
    return v;
}
__device__ __forceinline__ float warpMax(float v){
    #pragma unroll
    for(int o=16;o;o>>=1) v = fmaxf(v, __shfl_xor_sync(0xffffffffu, v, o));
    return v;
}
__device__ __forceinline__ unsigned f2tf(float f){
    unsigned r; asm("cvt.rna.tf32.f32 %0, %1;" : "=r"(r) : "f"(f)); return r;
}
__device__ __forceinline__ float tfround(float f){ return __uint_as_float(f2tf(f)); }
__device__ __forceinline__ void mma8(float* c, unsigned a0, unsigned a1, unsigned a2, unsigned a3,
                                     unsigned b0, unsigned b1){
    asm("mma.sync.aligned.m16n8k8.row.col.f32.tf32.tf32.f32 "
        "{%0,%1,%2,%3},{%4,%5,%6,%7},{%8,%9},{%0,%1,%2,%3};"
        : "+f"(c[0]),"+f"(c[1]),"+f"(c[2]),"+f"(c[3])
        : "r"(a0),"r"(a1),"r"(a2),"r"(a3),"r"(b0),"r"(b1));
}
__device__ __forceinline__ void cpa16(unsigned s, const void* g){
    asm volatile("cp.async.cg.shared.global [%0], [%1], 16;" :: "r"(s), "l"(g));
}

// ---------------- prep: trig table + weight tf32-rounding ----------------
__global__ void __launch_bounds__(256) k_prep(const float* __restrict__ Wq, const float* __restrict__ Wkv,
                                              const float* __restrict__ Wo,
                                              float* __restrict__ wq, float* __restrict__ wkv,
                                              float* __restrict__ wo, float* __restrict__ tab){
    int i = blockIdx.x*256 + threadIdx.x;          // < 532480
    if(i < 8192){
        int ii = i >> 4, fd = i & 15;
        float fr = (float)ii * expf(-(float)fd * FREQC);
        tab[ii*32 + fd]      = cosf(fr);
        tab[ii*32 + 16 + fd] = sinf(fr);
    }
    int j = i - 8192;
    if(j >= 0){
        if(j < 131072)       wq[j]         = tfround(Wq[j]);
        else if(j < 393216)  wkv[j-131072] = tfround(Wkv[j-131072]);
        else if(j < 524288)  wo[j-393216]  = tfround(Wo[j-393216]);
    }
}

// ---------------- pairwise distances ----------------
__global__ void __launch_bounds__(256) k_dist(const float* __restrict__ x, float* __restrict__ dist){
    int idx = blockIdx.x*256 + threadIdx.x;
    int j = idx & 511; int rest = idx >> 9;
    int i = rest & 511; int b = rest >> 9;
    const float* xi = x + (b*SN + i)*3;
    const float* xj = x + (b*SN + j)*3;
    float d0 = xi[0]-xj[0], d1 = xi[1]-xj[1], d2 = xi[2]-xj[2];
    float q = d0*d0 + d1*d1 + d2*d2;
    dist[idx] = (q > 0.f) ? sqrtf(q) : 0.f;
}

// ---------------- encoder + fused LN (warp per token) ----------------
__global__ void __launch_bounds__(256) k_encode(const float* __restrict__ x, const float* __restrict__ t,
                                                const float* __restrict__ W,
                                                const float* __restrict__ lng, const float* __restrict__ lnb,
                                                float* __restrict__ nodes, float* __restrict__ h){
    int w = threadIdx.x >> 5, lane = threadIdx.x & 31;
    int tok = blockIdx.x*8 + w;
    const float* xp = x + tok*3;
    float x0 = xp[0], x1 = xp[1], x2 = xp[2], tt = t[tok];
    float v[8]; float s = 0.f;
    #pragma unroll
    for(int k=0;k<8;k++){
        int c = lane + k*32;
        v[k] = x0*W[c] + x1*W[256+c] + x2*W[512+c] + tt*W[768+c];
        s += v[k];
    }
    s = warpSum(s);
    float mean = s * (1.f/DIM);
    float v2 = 0.f;
    #pragma unroll
    for(int k=0;k<8;k++){ float d = v[k]-mean; v2 = fmaf(d,d,v2); }
    v2 = warpSum(v2);
    float rstd = rsqrtf(v2*(1.f/DIM) + 1e-5f);
    #pragma unroll
    for(int k=0;k<8;k++){
        int c = lane + k*32;
        int idx = tok*DIM + c;
        nodes[idx] = v[k];
        h[idx] = tfround(fmaf((v[k]-mean)*rstd, lng[c], lnb[c]));
    }
}

// ============ tf32 GEMM, BK=32, NST=3, single barrier/iter, dynamic smem ============
template<bool QKV>
__global__ void __launch_bounds__(256) k_gemm_tc(const float* __restrict__ A,
        const float* __restrict__ W1, const float* __restrict__ b1,
        const float* __restrict__ W2, const float* __restrict__ b2,
        float* __restrict__ C){
    constexpr int BM=128, BK=32, BN=64, K=256, NST=3;
    constexpr int LDC = QKV ? 768 : 256;
    constexpr int AST = BK+4;        // 36
    constexpr int BSTR = BN+8;       // 72
    constexpr int ASZ = BM*AST;      // 4608 floats / stage
    constexpr int BSZ = BK*BSTR;     // 2304 floats / stage
    extern __shared__ float sm[];
    float* Asm = sm;                 // NST stages of ASZ
    float* Bsm = sm + NST*ASZ;       // NST stages of BSZ

    int tx = threadIdx.x;
    int wid = tx>>5, lane = tx&31;
    int bcol = blockIdx.x*BN, brow = blockIdx.y*BM;

    const float* W; const float* bias; int ldb;
    if(QKV){
        if(bcol < 256){ W = W1 + bcol;        bias = b1 + bcol;        ldb = 256; }
        else          { W = W2 + (bcol-256);  bias = b2 + (bcol-256);  ldb = 512; }
    } else {            W = W1 + bcol;        bias = b1 + bcol;        ldb = 256; }

    int ar[4], ak4[4];
    #pragma unroll
    for(int u=0;u<4;u++){ int f = tx + u*256; ar[u]=f>>3; ak4[u]=(f&7)*4; }
    int br[2], bc4[2];
    #pragma unroll
    for(int u=0;u<2;u++){ int f = tx + u*256; br[u]=f>>4; bc4[u]=(f&15)*4; }

    const float* Ab = A + brow*K;
    unsigned sA = (unsigned)__cvta_generic_to_shared(Asm);
    unsigned sB = (unsigned)__cvta_generic_to_shared(Bsm);
    unsigned saoff[4], sboff[2];
    #pragma unroll
    for(int u=0;u<4;u++) saoff[u] = (ar[u]*AST + ak4[u])*4u;
    #pragma unroll
    for(int u=0;u<2;u++) sboff[u] = (br[u]*BSTR + bc4[u])*4u;
    const float* ga[4]; const float* gb[2];
    #pragma unroll
    for(int u=0;u<4;u++) ga[u] = Ab + ar[u]*K + ak4[u];
    #pragma unroll
    for(int u=0;u<2;u++) gb[u] = W + br[u]*ldb + bc4[u];

    const int NT = K/BK;   // 8
    // prologue: tiles 0,1
    #pragma unroll
    for(int s=0;s<2;s++){
        unsigned a0 = sA + s*ASZ*4u, b0 = sB + s*BSZ*4u;
        #pragma unroll
        for(int u=0;u<4;u++) cpa16(a0 + saoff[u], ga[u] + s*BK);
        #pragma unroll
        for(int u=0;u<2;u++) cpa16(b0 + sboff[u], gb[u] + s*BK*ldb);
        asm volatile("cp.async.commit_group;" ::: "memory");
    }

    int wm = (wid & 3)*32, wn = (wid >> 2)*32;
    float acc[2][4][4];
    #pragma unroll
    for(int mt=0;mt<2;mt++)
        #pragma unroll
        for(int nt=0;nt<4;nt++)
            #pragma unroll
            for(int e=0;e<4;e++) acc[mt][nt][e] = 0.f;

    for(int t=0;t<NT;t++){
        asm volatile("cp.async.wait_group 1;" ::: "memory");
        __syncthreads();
        // issue loads for tile t+2 into slot (t+2)%NST (== slot of consumed tile t-1)
        int lt = t+2;
        if(lt < NT){
            int slot = lt % NST;
            unsigned a0 = sA + slot*ASZ*4u, b0 = sB + slot*BSZ*4u;
            #pragma unroll
            for(int u=0;u<4;u++) cpa16(a0 + saoff[u], ga[u] + lt*BK);
            #pragma unroll
            for(int u=0;u<2;u++) cpa16(b0 + sboff[u], gb[u] + lt*BK*ldb);
        }
        asm volatile("cp.async.commit_group;" ::: "memory");

        const float* As_ = Asm + (t%NST)*ASZ;
        const float* Bs_ = Bsm + (t%NST)*BSZ;
        #pragma unroll
        for(int ks=0;ks<4;ks++){
            int kq = ks*8 + (lane&3);
            unsigned a[2][4], b[4][2];
            int arow = wm + (lane>>2);
            #pragma unroll
            for(int mt=0;mt<2;mt++){
                int r = arow + mt*16;
                a[mt][0] = __float_as_uint(As_[ r   *AST + kq  ]);
                a[mt][1] = __float_as_uint(As_[(r+8)*AST + kq  ]);
                a[mt][2] = __float_as_uint(As_[ r   *AST + kq+4]);
                a[mt][3] = __float_as_uint(As_[(r+8)*AST + kq+4]);
            }
            int bc0 = wn + (lane>>2);
            #pragma unroll
            for(int nt=0;nt<4;nt++){
                b[nt][0] = __float_as_uint(Bs_[ kq   *BSTR + bc0 + nt*8]);
                b[nt][1] = __float_as_uint(Bs_[(kq+4)*BSTR + bc0 + nt*8]);
            }
            #pragma unroll
            for(int mt=0;mt<2;mt++)
                #pragma unroll
                for(int nt=0;nt<4;nt++)
                    mma8(acc[mt][nt], a[mt][0],a[mt][1],a[mt][2],a[mt][3], b[nt][0],b[nt][1]);
        }
    }

    #pragma unroll
    for(int mt=0;mt<2;mt++){
        int r = brow + wm + mt*16 + (lane>>2);
        #pragma unroll
        for(int nt=0;nt<4;nt++){
            int lc = wn + nt*8 + (lane&3)*2;
            float bz0 = bias[lc], bz1 = bias[lc+1];
            float* c0p = C + r*LDC + bcol + lc;
            c0p[0] = acc[mt][nt][0] + bz0;
            c0p[1] = acc[mt][nt][1] + bz1;
            float* c1p = C + (r+8)*LDC + bcol + lc;
            c1p[0] = acc[mt][nt][2] + bz0;
            c1p[1] = acc[mt][nt][3] + bz1;
        }
    }
}

// ---------------- rotary Q/K (+ q.We, q.be) + V relayout ----------------
__global__ void __launch_bounds__(256) k_rot(const float* __restrict__ qkv,
                                             const float* __restrict__ We, const float* __restrict__ be,
                                             const float* __restrict__ tab,
                                             float* __restrict__ q, float* __restrict__ qwe, float* __restrict__ qbe,
                                             float* __restrict__ kt, float* __restrict__ v){
    int bi = blockIdx.x;
    int b = bi >> 9, i = bi & 511;
    int h = threadIdx.x >> 5, d = threadIdx.x & 31;
    int bh = b*NH + h;
    const float* row = qkv + bi*768;
    int fd = d & 15;
    float cs = tab[i*32 + fd];
    float sn = tab[i*32 + 16 + fd];

    float qv = row[h*32 + d];
    float qo = row[h*32 + ((d+16)&31)];
    float qrot = (d < 16) ? -qo : qo;
    float qval = (qv*cs + qrot*sn) * QSCALE;
    q[(bh*SN + i)*HD + d] = qval;

    float kv = row[256 + h*32 + d];
    float ko = row[256 + h*32 + ((d+16)&31)];
    float krot = (d < 16) ? -ko : ko;
    kt[(bh*HD + d)*SN + i] = kv*cs + krot*sn;

    v[(bh*SN + i)*HD + d] = row[512 + h*32 + d];

    float dwe = warpSum(qval * We[h*32 + d]);
    float dbe = warpSum(qval * be[h*32 + d]);
    if(d == 0){ qwe[bh*SN + i] = dwe; qbe[bh*SN + i] = dbe; }
}

// ---------------- attention: warp handles 2 query rows ----------------
__global__ void __launch_bounds__(256) k_attn2(
    const float* __restrict__ q, const float* __restrict__ kt, const float* __restrict__ v,
    const float* __restrict__ qwe, const float* __restrict__ qbe, const float* __restrict__ dist,
    const float* __restrict__ We, const float* __restrict__ be, float* __restrict__ out)
{
    __shared__ __align__(16) float sp[16][512];
    int w = threadIdx.x >> 5, lane = threadIdx.x & 31;
    int bh = blockIdx.x >> 5;
    int chunk = blockIdx.x & 31;
    int b = bh >> 3, h = bh & 7;
    int i0 = chunk*16 + w*2, i1 = i0 + 1;

    float qr0[32], qr1[32];
    {
        float qv0 = q[(bh*SN + i0)*HD + lane];
        float qv1 = q[(bh*SN + i1)*HD + lane];
        #pragma unroll
        for(int d=0;d<32;d++){ qr0[d] = __shfl_sync(0xffffffffu, qv0, d);
                               qr1[d] = __shfl_sync(0xffffffffu, qv1, d); }
    }
    float cwe0 = qwe[bh*SN + i0], cwe1 = qwe[bh*SN + i1];
    float cbe0 = qbe[bh*SN + i0], cbe1 = qbe[bh*SN + i1];
    const float* Kt = kt + bh*HD*SN;
    const float* D0 = dist + (b*SN + i0)*SN;
    const float* D1 = dist + (b*SN + i1)*SN;

    float m0 = -1e30f, m1 = -1e30f;
    #pragma unroll
    for(int cb=0;cb<4;cb++){
        int j0 = cb*128 + lane*4;
        float4 s0 = make_float4(cbe0,cbe0,cbe0,cbe0);
        float4 s1 = make_float4(cbe1,cbe1,cbe1,cbe1);
        #pragma unroll
        for(int d=0;d<32;d++){
            float4 kk = *(const float4*)(Kt + d*SN + j0);
            s0.x = fmaf(qr0[d], kk.x, s0.x); s0.y = fmaf(qr0[d], kk.y, s0.y);
            s0.z = fmaf(qr0[d], kk.z, s0.z); s0.w = fmaf(qr0[d], kk.w, s0.w);
            s1.x = fmaf(qr1[d], kk.x, s1.x); s1.y = fmaf(qr1[d], kk.y, s1.y);
            s1.z = fmaf(qr1[d], kk.z, s1.z); s1.w = fmaf(qr1[d], kk.w, s1.w);
        }
        float4 d0 = *(const float4*)(D0 + j0);
        float4 d1 = *(const float4*)(D1 + j0);
        s0.x = fmaf(d0.x, cwe0, s0.x); s0.y = fmaf(d0.y, cwe0, s0.y);
        s0.z = fmaf(d0.z, cwe0, s0.z); s0.w = fmaf(d0.w, cwe0, s0.w);
        s1.x = fmaf(d1.x, cwe1, s1.x); s1.y = fmaf(d1.y, cwe1, s1.y);
        s1.z = fmaf(d1.z, cwe1, s1.z); s1.w = fmaf(d1.w, cwe1, s1.w);
        *(float4*)&sp[w*2  ][j0] = s0;
        *(float4*)&sp[w*2+1][j0] = s1;
        m0 = fmaxf(m0, fmaxf(fmaxf(s0.x,s0.y), fmaxf(s0.z,s0.w)));
        m1 = fmaxf(m1, fmaxf(fmaxf(s1.x,s1.y), fmaxf(s1.z,s1.w)));
    }
    m0 = warpMax(m0); m1 = warpMax(m1);

    float sum0 = 0.f, sum1 = 0.f, sd0 = 0.f, sd1 = 0.f;
    #pragma unroll
    for(int cb=0;cb<4;cb++){
        int j0 = cb*128 + lane*4;
        float4 s0 = *(const float4*)&sp[w*2  ][j0];
        float4 s1 = *(const float4*)&sp[w*2+1][j0];
        float4 d0 = *(const float4*)(D0 + j0);
        float4 d1 = *(const float4*)(D1 + j0);
        float4 p0, p1;
        p0.x = __expf(s0.x-m0); p0.y = __expf(s0.y-m0); p0.z = __expf(s0.z-m0); p0.w = __expf(s0.w-m0);
        p1.x = __expf(s1.x-m1); p1.y = __expf(s1.y-m1); p1.z = __expf(s1.z-m1); p1.w = __expf(s1.w-m1);
        sum0 += (p0.x+p0.y)+(p0.z+p0.w);
        sum1 += (p1.x+p1.y)+(p1.z+p1.w);
        sd0 = fmaf(p0.x,d0.x,sd0); sd0 = fmaf(p0.y,d0.y,sd0); sd0 = fmaf(p0.z,d0.z,sd0); sd0 = fmaf(p0.w,d0.w,sd0);
        sd1 = fmaf(p1.x,d1.x,sd1); sd1 = fmaf(p1.y,d1.y,sd1); sd1 = fmaf(p1.z,d1.z,sd1); sd1 = fmaf(p1.w,d1.w,sd1);
        *(float4*)&sp[w*2  ][j0] = p0;
        *(float4*)&sp[w*2+1][j0] = p1;
    }
    sum0 = warpSum(sum0); sum1 = warpSum(sum1);
    sd0  = warpSum(sd0);  sd1  = warpSum(sd1);
    float inv0 = 1.f/sum0, inv1 = 1.f/sum1;
    __syncwarp();

    const float* Vp = v + bh*SN*HD;
    const float4* p0v = (const float4*)sp[w*2];
    const float4* p1v = (const float4*)sp[w*2+1];
    float a00=0.f,a01=0.f,a02=0.f,a03=0.f;
    float a10=0.f,a11=0.f,a12=0.f,a13=0.f;
    #pragma unroll 4
    for(int j4=0;j4<128;j4++){
        float4 p0 = p0v[j4];
        float4 p1 = p1v[j4];
        const float* vb = Vp + j4*128 + lane;
        float v0 = vb[0], v1 = vb[32], v2 = vb[64], v3 = vb[96];
        a00 = fmaf(p0.x,v0,a00); a01 = fmaf(p0.y,v1,a01);
        a02 = fmaf(p0.z,v2,a02); a03 = fmaf(p0.w,v3,a03);
        a10 = fmaf(p1.x,v0,a10); a11 = fmaf(p1.y,v1,a11);
        a12 = fmaf(p1.z,v2,a12); a13 = fmaf(p1.w,v3,a13);
    }
    float a0 = (a00+a01)+(a02+a03);
    float a1 = (a10+a11)+(a12+a13);
    float wl = We[h*32 + lane], bl = be[h*32 + lane];
    out[((b*SN + i0)*NH + h)*HD + lane] = tfround(a0*inv0 + (sd0*inv0)*wl + bl);
    out[((b*SN + i1)*NH + h)*HD + lane] = tfround(a1*inv1 + (sd1*inv1)*wl + bl);
}

// ---------------- gate + residual, fused next-LN (l=0) or fused decode (l=1) ----------------
template<bool LAST>
__global__ void __launch_bounds__(256) k_gate(const float* __restrict__ o, const float* __restrict__ wg,
                                              float* __restrict__ nodes,
                                              const float* __restrict__ lng, const float* __restrict__ lnb,
                                              float* __restrict__ h,
                                              const float* __restrict__ Wd, float* __restrict__ out){
    int w = threadIdx.x >> 5, lane = threadIdx.x & 31;
    int tok = blockIdx.x*8 + w;
    const float* op = o + tok*DIM;
    float* np = nodes + tok*DIM;
    float ov[8], nv[8];
    float s = 0.f;
    #pragma unroll
    for(int k=0;k<8;k++){
        int c = lane + k*32;
        ov[k] = op[c]; nv[k] = np[c];
        s = fmaf(ov[k], wg[c] + wg[512+c], s);
        s = fmaf(nv[k], wg[256+c] - wg[512+c], s);
    }
    s = warpSum(s);
    float g = 1.f / (1.f + __expf(-s));
    float newv[8];
    float vs = 0.f;
    #pragma unroll
    for(int k=0;k<8;k++){
        newv[k] = ov[k]*g + nv[k]*(1.f - g);
        vs += newv[k];
    }
    if(!LAST){
        vs = warpSum(vs);
        float mean = vs * (1.f/DIM);
        float v2 = 0.f;
        #pragma unroll
        for(int k=0;k<8;k++){ float d = newv[k]-mean; v2 = fmaf(d,d,v2); }
        v2 = warpSum(v2);
        float rstd = rsqrtf(v2*(1.f/DIM) + 1e-5f);
        #pragma unroll
        for(int k=0;k<8;k++){
            int c = lane + k*32;
            np[c] = newv[k];
            h[tok*DIM + c] = tfround(fmaf((newv[k]-mean)*rstd, lng[c], lnb[c]));
        }
    } else {
        float a0 = 0.f, a1 = 0.f, a2 = 0.f;
        #pragma unroll
        for(int k=0;k<8;k++){
            int c = lane + k*32;
            a0 = fmaf(newv[k], Wd[c*3+0], a0);
            a1 = fmaf(newv[k], Wd[c*3+1], a1);
            a2 = fmaf(newv[k], Wd[c*3+2], a2);
        }
        a0 = warpSum(a0); a1 = warpSum(a1); a2 = warpSum(a2);
        if(lane == 0){
            out[tok*3+0] = a0; out[tok*3+1] = a1; out[tok*3+2] = a2;
        }
    }
}

// ---------------- launch ----------------
extern "C" void kernel_launch(void* const* d_in, const int* in_sizes, int n_in,
                              void* d_out, int out_size){
    (void)in_sizes; (void)n_in; (void)out_size;
    const float* x     = (const float*)d_in[0];
    const float* t     = (const float*)d_in[1];
    const float* W_enc = (const float*)d_in[2];
    const float* W_dec = (const float*)d_in[3];
    const float* ln_g  = (const float*)d_in[4];
    const float* ln_b  = (const float*)d_in[5];
    const float* Wq    = (const float*)d_in[6];
    const float* bq    = (const float*)d_in[7];
    const float* Wkv   = (const float*)d_in[8];
    const float* bkv   = (const float*)d_in[9];
    const float* We    = (const float*)d_in[10];
    const float* be    = (const float*)d_in[11];
    const float* Wo    = (const float*)d_in[12];
    const float* bo    = (const float*)d_in[13];
    const float* Wg    = (const float*)d_in[14];
    float* out = (float*)d_out;

    float *dist,*nodes,*h,*qkv,*q,*kt,*v,*qwe,*qbe,*attno,*ofull,*tab,*wq,*wkv,*wo;
    cudaGetSymbolAddress((void**)&dist,  g_dist);
    cudaGetSymbolAddress((void**)&nodes, g_nodes);
    cudaGetSymbolAddress((void**)&h,     g_h);
    cudaGetSymbolAddress((void**)&qkv,   g_qkv);
    cudaGetSymbolAddress((void**)&q,     g_q);
    cudaGetSymbolAddress((void**)&kt,    g_kt);
    cudaGetSymbolAddress((void**)&v,     g_v);
    cudaGetSymbolAddress((void**)&qwe,   g_qwe);
    cudaGetSymbolAddress((void**)&qbe,   g_qbe);
    cudaGetSymbolAddress((void**)&attno, g_attno);
    cudaGetSymbolAddress((void**)&ofull, g_out);
    cudaGetSymbolAddress((void**)&tab,   g_tab);
    cudaGetSymbolAddress((void**)&wq,    g_wq);
    cudaGetSymbolAddress((void**)&wkv,   g_wkv);
    cudaGetSymbolAddress((void**)&wo,    g_wo);

    const int gemm_smem = 3*(128*36 + 32*72)*4;   // 82944 bytes
    cudaFuncSetAttribute(k_gemm_tc<true>,  cudaFuncAttributeMaxDynamicSharedMemorySize, gemm_smem);
    cudaFuncSetAttribute(k_gemm_tc<false>, cudaFuncAttributeMaxDynamicSharedMemorySize, gemm_smem);

    // side stream: prep (needed by first GEMM) then dist (needed by first attn)
    cudaStream_t sB;
    cudaStreamCreateWithFlags(&sB, cudaStreamNonBlocking);
    cudaEvent_t eF, eP, eJ;
    cudaEventCreateWithFlags(&eF, cudaEventDisableTiming);
    cudaEventCreateWithFlags(&eP, cudaEventDisableTiming);
    cudaEventCreateWithFlags(&eJ, cudaEventDisableTiming);
    cudaEventRecord(eF, 0);
    cudaStreamWaitEvent(sB, eF, 0);
    k_prep<<<2080,256,0,sB>>>(Wq, Wkv, Wo, wq, wkv, wo, tab);
    cudaEventRecord(eP, sB);
    k_dist<<<2048,256,0,sB>>>(x, dist);
    cudaEventRecord(eJ, sB);

    k_encode<<<128,256>>>(x, t, W_enc, ln_g, ln_b, nodes, h);
    cudaStreamWaitEvent(0, eP, 0);

    for(int l=0;l<2;l++){
        k_gemm_tc<true><<<dim3(12,8),256,gemm_smem>>>(h, wq + l*DIM*DIM, bq + l*DIM,
                                            wkv + l*DIM*2*DIM, bkv + l*2*DIM, qkv);
        k_rot<<<1024,256>>>(qkv, We + l*DIM, be + l*DIM, tab, q, qwe, qbe, kt, v);
        if(l == 0) cudaStreamWaitEvent(0, eJ, 0);
        k_attn2<<<512,256>>>(q, kt, v, qwe, qbe, dist, We + l*DIM, be + l*DIM, attno);
        k_gemm_tc<false><<<dim3(4,8),256,gemm_smem>>>(attno, wo + l*DIM*DIM, bo + l*DIM,
                                            nullptr, nullptr, ofull);
        if(l == 0)
            k_gate<false><<<128,256>>>(ofull, Wg, nodes, ln_g + DIM, ln_b + DIM, h,
                                       nullptr, nullptr);
        else
            k_gate<true><<<128,256>>>(ofull, Wg + 3*DIM, nodes, nullptr, nullptr, nullptr,
                                      W_dec, out);
    }
}

// round 10
// speedup vs baseline: 1.0379x; 1.0379x over previous
#include <cuda_runtime.h>
#include <math.h>

#define NB 2
#define SN 512
#define DIM 256
#define NH 8
#define HD 32
#define QSCALE 0.17677669529663689f   // 1/sqrt(32)
#define FREQC  0.5756462732485115f    // ln(10000)/16

// ---------------- scratch (device globals) ----------------
__device__ __align__(256) float g_dist [NB*SN*SN];
__device__ __align__(256) float g_nodes[NB*SN*DIM];
__device__ __align__(256) float g_h    [NB*SN*DIM];
__device__ __align__(256) float g_qkv  [NB*SN*3*DIM];
__device__ __align__(256) float g_q    [NB*NH*SN*HD];
__device__ __align__(256) float g_kt   [NB*NH*HD*SN];
__device__ __align__(256) float g_v    [NB*NH*SN*HD];
__device__ __align__(256) float g_qwe  [NB*NH*SN];
__device__ __align__(256) float g_qbe  [NB*NH*SN];
__device__ __align__(256) float g_attno[NB*SN*DIM];
__device__ __align__(256) float g_out  [NB*SN*DIM];
__device__ __align__(256) float g_tab  [SN*32];
__device__ __align__(256) float g_wq   [2*DIM*DIM];
__device__ __align__(256) float g_wkv  [2*DIM*2*DIM];
__device__ __align__(256) float g_wo   [2*DIM*DIM];

// ---------------- helpers ----------------
__device__ __forceinline__ float warpSum(float v){
    #pragma unroll
    for(int o=16;o;o>>=1) v += __shfl_xor_sync(0xffffffffu, v, o);
    return v;
}
__device__ __forceinline__ float warpMax(float v){
    #pragma unroll
    for(int o=16;o;o>>=1) v = fmaxf(v, __shfl_xor_sync(0xffffffffu, v, o));
    return v;
}
__device__ __forceinline__ unsigned f2tf(float f){
    unsigned r; asm("cvt.rna.tf32.f32 %0, %1;" : "=r"(r) : "f"(f)); return r;
}
__device__ __forceinline__ float tfround(float f){ return __uint_as_float(f2tf(f)); }
__device__ __forceinline__ void mma8(float* c, unsigned a0, unsigned a1, unsigned a2, unsigned a3,
                                     unsigned b0, unsigned b1){
    asm("mma.sync.aligned.m16n8k8.row.col.f32.tf32.tf32.f32 "
        "{%0,%1,%2,%3},{%4,%5,%6,%7},{%8,%9},{%0,%1,%2,%3};"
        : "+f"(c[0]),"+f"(c[1]),"+f"(c[2]),"+f"(c[3])
        : "r"(a0),"r"(a1),"r"(a2),"r"(a3),"r"(b0),"r"(b1));
}
__device__ __forceinline__ void cpa16(unsigned s, const void* g){
    asm volatile("cp.async.cg.shared.global [%0], [%1], 16;" :: "r"(s), "l"(g));
}

// ---------------- prep: trig table + weight tf32-rounding ----------------
__global__ void __launch_bounds__(256) k_prep(const float* __restrict__ Wq, const float* __restrict__ Wkv,
                                              const float* __restrict__ Wo,
                                              float* __restrict__ wq, float* __restrict__ wkv,
                                              float* __restrict__ wo, float* __restrict__ tab){
    int i = blockIdx.x*256 + threadIdx.x;          // < 532480
    if(i < 8192){
        int ii = i >> 4, fd = i & 15;
        float fr = (float)ii * expf(-(float)fd * FREQC);
        tab[ii*32 + fd]      = cosf(fr);
        tab[ii*32 + 16 + fd] = sinf(fr);
    }
    int j = i - 8192;
    if(j >= 0){
        if(j < 131072)       wq[j]         = tfround(Wq[j]);
        else if(j < 393216)  wkv[j-131072] = tfround(Wkv[j-131072]);
        else if(j < 524288)  wo[j-393216]  = tfround(Wo[j-393216]);
    }
}

// ---------------- pairwise distances ----------------
__global__ void __launch_bounds__(256) k_dist(const float* __restrict__ x, float* __restrict__ dist){
    int idx = blockIdx.x*256 + threadIdx.x;
    int j = idx & 511; int rest = idx >> 9;
    int i = rest & 511; int b = rest >> 9;
    const float* xi = x + (b*SN + i)*3;
    const float* xj = x + (b*SN + j)*3;
    float d0 = xi[0]-xj[0], d1 = xi[1]-xj[1], d2 = xi[2]-xj[2];
    float q = d0*d0 + d1*d1 + d2*d2;
    dist[idx] = (q > 0.f) ? sqrtf(q) : 0.f;
}

// ---------------- encoder + fused LN (warp per token) ----------------
__global__ void __launch_bounds__(256) k_encode(const float* __restrict__ x, const float* __restrict__ t,
                                                const float* __restrict__ W,
                                                const float* __restrict__ lng, const float* __restrict__ lnb,
                                                float* __restrict__ nodes, float* __restrict__ h){
    int w = threadIdx.x >> 5, lane = threadIdx.x & 31;
    int tok = blockIdx.x*8 + w;
    const float* xp = x + tok*3;
    float x0 = xp[0], x1 = xp[1], x2 = xp[2], tt = t[tok];
    float v[8]; float s = 0.f;
    #pragma unroll
    for(int k=0;k<8;k++){
        int c = lane + k*32;
        v[k] = x0*W[c] + x1*W[256+c] + x2*W[512+c] + tt*W[768+c];
        s += v[k];
    }
    s = warpSum(s);
    float mean = s * (1.f/DIM);
    float v2 = 0.f;
    #pragma unroll
    for(int k=0;k<8;k++){ float d = v[k]-mean; v2 = fmaf(d,d,v2); }
    v2 = warpSum(v2);
    float rstd = rsqrtf(v2*(1.f/DIM) + 1e-5f);
    #pragma unroll
    for(int k=0;k<8;k++){
        int c = lane + k*32;
        int idx = tok*DIM + c;
        nodes[idx] = v[k];
        h[idx] = tfround(fmaf((v[k]-mean)*rstd, lng[c], lnb[c]));
    }
}

// ============ tf32 GEMM: BM=64, BN=64, BK=32, NST=3, 8 warps (4x2), dyn smem ============
// QKV: grid (12,16) C[1024,768]; else grid (4,16) C[1024,256]
template<bool QKV>
__global__ void __launch_bounds__(256) k_gemm_tc(const float* __restrict__ A,
        const float* __restrict__ W1, const float* __restrict__ b1,
        const float* __restrict__ W2, const float* __restrict__ b2,
        float* __restrict__ C){
    constexpr int BM=64, BK=32, BN=64, K=256, NST=3;
    constexpr int LDC = QKV ? 768 : 256;
    constexpr int AST = BK+4;        // 36
    constexpr int BSTR = BN+8;       // 72
    constexpr int ASZ = BM*AST;      // 2304 floats / stage
    constexpr int BSZ = BK*BSTR;     // 2304 floats / stage
    extern __shared__ float sm[];
    float* Asm = sm;
    float* Bsm = sm + NST*ASZ;

    int tx = threadIdx.x;
    int wid = tx>>5, lane = tx&31;
    int bcol = blockIdx.x*BN, brow = blockIdx.y*BM;

    const float* W; const float* bias; int ldb;
    if(QKV){
        if(bcol < 256){ W = W1 + bcol;        bias = b1 + bcol;        ldb = 256; }
        else          { W = W2 + (bcol-256);  bias = b2 + (bcol-256);  ldb = 512; }
    } else {            W = W1 + bcol;        bias = b1 + bcol;        ldb = 256; }

    int ar[2], ak4[2];
    #pragma unroll
    for(int u=0;u<2;u++){ int f = tx + u*256; ar[u]=f>>3; ak4[u]=(f&7)*4; }
    int br[2], bc4[2];
    #pragma unroll
    for(int u=0;u<2;u++){ int f = tx + u*256; br[u]=f>>4; bc4[u]=(f&15)*4; }

    const float* Ab = A + brow*K;
    unsigned sA = (unsigned)__cvta_generic_to_shared(Asm);
    unsigned sB = (unsigned)__cvta_generic_to_shared(Bsm);
    unsigned saoff[2], sboff[2];
    #pragma unroll
    for(int u=0;u<2;u++) saoff[u] = (ar[u]*AST + ak4[u])*4u;
    #pragma unroll
    for(int u=0;u<2;u++) sboff[u] = (br[u]*BSTR + bc4[u])*4u;
    const float* ga[2]; const float* gb[2];
    #pragma unroll
    for(int u=0;u<2;u++) ga[u] = Ab + ar[u]*K + ak4[u];
    #pragma unroll
    for(int u=0;u<2;u++) gb[u] = W + br[u]*ldb + bc4[u];

    const int NT = K/BK;   // 8
    #pragma unroll
    for(int s=0;s<2;s++){
        unsigned a0 = sA + s*ASZ*4u, b0 = sB + s*BSZ*4u;
        #pragma unroll
        for(int u=0;u<2;u++) cpa16(a0 + saoff[u], ga[u] + s*BK);
        #pragma unroll
        for(int u=0;u<2;u++) cpa16(b0 + sboff[u], gb[u] + s*BK*ldb);
        asm volatile("cp.async.commit_group;" ::: "memory");
    }

    int wm = (wid & 3)*16, wn = (wid >> 2)*32;
    float acc[4][4];
    #pragma unroll
    for(int nt=0;nt<4;nt++)
        #pragma unroll
        for(int e=0;e<4;e++) acc[nt][e] = 0.f;

    for(int t=0;t<NT;t++){
        asm volatile("cp.async.wait_group 1;" ::: "memory");
        __syncthreads();
        int lt = t+2;
        if(lt < NT){
            int slot = lt % NST;
            unsigned a0 = sA + slot*ASZ*4u, b0 = sB + slot*BSZ*4u;
            #pragma unroll
            for(int u=0;u<2;u++) cpa16(a0 + saoff[u], ga[u] + lt*BK);
            #pragma unroll
            for(int u=0;u<2;u++) cpa16(b0 + sboff[u], gb[u] + lt*BK*ldb);
        }
        asm volatile("cp.async.commit_group;" ::: "memory");

        const float* As_ = Asm + (t%NST)*ASZ;
        const float* Bs_ = Bsm + (t%NST)*BSZ;
        #pragma unroll
        for(int ks=0;ks<4;ks++){
            int kq = ks*8 + (lane&3);
            int arow = wm + (lane>>2);
            unsigned a0 = __float_as_uint(As_[ arow   *AST + kq  ]);
            unsigned a1 = __float_as_uint(As_[(arow+8)*AST + kq  ]);
            unsigned a2 = __float_as_uint(As_[ arow   *AST + kq+4]);
            unsigned a3 = __float_as_uint(As_[(arow+8)*AST + kq+4]);
            int bc0 = wn + (lane>>2);
            unsigned b[4][2];
            #pragma unroll
            for(int nt=0;nt<4;nt++){
                b[nt][0] = __float_as_uint(Bs_[ kq   *BSTR + bc0 + nt*8]);
                b[nt][1] = __float_as_uint(Bs_[(kq+4)*BSTR + bc0 + nt*8]);
            }
            #pragma unroll
            for(int nt=0;nt<4;nt++)
                mma8(acc[nt], a0,a1,a2,a3, b[nt][0],b[nt][1]);
        }
    }

    {
        int r = brow + wm + (lane>>2);
        #pragma unroll
        for(int nt=0;nt<4;nt++){
            int lc = wn + nt*8 + (lane&3)*2;
            float bz0 = bias[lc], bz1 = bias[lc+1];
            float* c0p = C + r*LDC + bcol + lc;
            c0p[0] = acc[nt][0] + bz0;
            c0p[1] = acc[nt][1] + bz1;
            float* c1p = C + (r+8)*LDC + bcol + lc;
            c1p[0] = acc[nt][2] + bz0;
            c1p[1] = acc[nt][3] + bz1;
        }
    }
}

// ---------------- rotary Q/K (+ q.We, q.be) + V relayout ----------------
__global__ void __launch_bounds__(256) k_rot(const float* __restrict__ qkv,
                                             const float* __restrict__ We, const float* __restrict__ be,
                                             const float* __restrict__ tab,
                                             float* __restrict__ q, float* __restrict__ qwe, float* __restrict__ qbe,
                                             float* __restrict__ kt, float* __restrict__ v){
    int bi = blockIdx.x;
    int b = bi >> 9, i = bi & 511;
    int h = threadIdx.x >> 5, d = threadIdx.x & 31;
    int bh = b*NH + h;
    const float* row = qkv + bi*768;
    int fd = d & 15;
    float cs = tab[i*32 + fd];
    float sn = tab[i*32 + 16 + fd];

    float qv = row[h*32 + d];
    float qo = row[h*32 + ((d+16)&31)];
    float qrot = (d < 16) ? -qo : qo;
    float qval = (qv*cs + qrot*sn) * QSCALE;
    q[(bh*SN + i)*HD + d] = qval;

    float kv = row[256 + h*32 + d];
    float ko = row[256 + h*32 + ((d+16)&31)];
    float krot = (d < 16) ? -ko : ko;
    kt[(bh*HD + d)*SN + i] = kv*cs + krot*sn;

    v[(bh*SN + i)*HD + d] = row[512 + h*32 + d];

    float dwe = warpSum(qval * We[h*32 + d]);
    float dbe = warpSum(qval * be[h*32 + d]);
    if(d == 0){ qwe[bh*SN + i] = dwe; qbe[bh*SN + i] = dbe; }
}

// ---------------- attention: warp handles 2 query rows ----------------
__global__ void __launch_bounds__(256) k_attn2(
    const float* __restrict__ q, const float* __restrict__ kt, const float* __restrict__ v,
    const float* __restrict__ qwe, const float* __restrict__ qbe, const float* __restrict__ dist,
    const float* __restrict__ We, const float* __restrict__ be, float* __restrict__ out)
{
    __shared__ __align__(16) float sp[16][512];
    int w = threadIdx.x >> 5, lane = threadIdx.x & 31;
    int bh = blockIdx.x >> 5;
    int chunk = blockIdx.x & 31;
    int b = bh >> 3, h = bh & 7;
    int i0 = chunk*16 + w*2, i1 = i0 + 1;

    float qr0[32], qr1[32];
    {
        float qv0 = q[(bh*SN + i0)*HD + lane];
        float qv1 = q[(bh*SN + i1)*HD + lane];
        #pragma unroll
        for(int d=0;d<32;d++){ qr0[d] = __shfl_sync(0xffffffffu, qv0, d);
                               qr1[d] = __shfl_sync(0xffffffffu, qv1, d); }
    }
    float cwe0 = qwe[bh*SN + i0], cwe1 = qwe[bh*SN + i1];
    float cbe0 = qbe[bh*SN + i0], cbe1 = qbe[bh*SN + i1];
    const float* Kt = kt + bh*HD*SN;
    const float* D0 = dist + (b*SN + i0)*SN;
    const float* D1 = dist + (b*SN + i1)*SN;

    float m0 = -1e30f, m1 = -1e30f;
    #pragma unroll
    for(int cb=0;cb<4;cb++){
        int j0 = cb*128 + lane*4;
        float4 s0 = make_float4(cbe0,cbe0,cbe0,cbe0);
        float4 s1 = make_float4(cbe1,cbe1,cbe1,cbe1);
        #pragma unroll
        for(int d=0;d<32;d++){
            float4 kk = *(const float4*)(Kt + d*SN + j0);
            s0.x = fmaf(qr0[d], kk.x, s0.x); s0.y = fmaf(qr0[d], kk.y, s0.y);
            s0.z = fmaf(qr0[d], kk.z, s0.z); s0.w = fmaf(qr0[d], kk.w, s0.w);
            s1.x = fmaf(qr1[d], kk.x, s1.x); s1.y = fmaf(qr1[d], kk.y, s1.y);
            s1.z = fmaf(qr1[d], kk.z, s1.z); s1.w = fmaf(qr1[d], kk.w, s1.w);
        }
        float4 d0 = *(const float4*)(D0 + j0);
        float4 d1 = *(const float4*)(D1 + j0);
        s0.x = fmaf(d0.x, cwe0, s0.x); s0.y = fmaf(d0.y, cwe0, s0.y);
        s0.z = fmaf(d0.z, cwe0, s0.z); s0.w = fmaf(d0.w, cwe0, s0.w);
        s1.x = fmaf(d1.x, cwe1, s1.x); s1.y = fmaf(d1.y, cwe1, s1.y);
        s1.z = fmaf(d1.z, cwe1, s1.z); s1.w = fmaf(d1.w, cwe1, s1.w);
        *(float4*)&sp[w*2  ][j0] = s0;
        *(float4*)&sp[w*2+1][j0] = s1;
        m0 = fmaxf(m0, fmaxf(fmaxf(s0.x,s0.y), fmaxf(s0.z,s0.w)));
        m1 = fmaxf(m1, fmaxf(fmaxf(s1.x,s1.y), fmaxf(s1.z,s1.w)));
    }
    m0 = warpMax(m0); m1 = warpMax(m1);

    float sum0 = 0.f, sum1 = 0.f, sd0 = 0.f, sd1 = 0.f;
    #pragma unroll
    for(int cb=0;cb<4;cb++){
        int j0 = cb*128 + lane*4;
        float4 s0 = *(const float4*)&sp[w*2  ][j0];
        float4 s1 = *(const float4*)&sp[w*2+1][j0];
        float4 d0 = *(const float4*)(D0 + j0);
        float4 d1 = *(const float4*)(D1 + j0);
        float4 p0, p1;
        p0.x = __expf(s0.x-m0); p0.y = __expf(s0.y-m0); p0.z = __expf(s0.z-m0); p0.w = __expf(s0.w-m0);
        p1.x = __expf(s1.x-m1); p1.y = __expf(s1.y-m1); p1.z = __expf(s1.z-m1); p1.w = __expf(s1.w-m1);
        sum0 += (p0.x+p0.y)+(p0.z+p0.w);
        sum1 += (p1.x+p1.y)+(p1.z+p1.w);
        sd0 = fmaf(p0.x,d0.x,sd0); sd0 = fmaf(p0.y,d0.y,sd0); sd0 = fmaf(p0.z,d0.z,sd0); sd0 = fmaf(p0.w,d0.w,sd0);
        sd1 = fmaf(p1.x,d1.x,sd1); sd1 = fmaf(p1.y,d1.y,sd1); sd1 = fmaf(p1.z,d1.z,sd1); sd1 = fmaf(p1.w,d1.w,sd1);
        *(float4*)&sp[w*2  ][j0] = p0;
        *(float4*)&sp[w*2+1][j0] = p1;
    }
    sum0 = warpSum(sum0); sum1 = warpSum(sum1);
    sd0  = warpSum(sd0);  sd1  = warpSum(sd1);
    float inv0 = 1.f/sum0, inv1 = 1.f/sum1;
    __syncwarp();

    const float* Vp = v + bh*SN*HD;
    const float4* p0v = (const float4*)sp[w*2];
    const float4* p1v = (const float4*)sp[w*2+1];
    float a00=0.f,a01=0.f,a02=0.f,a03=0.f;
    float a10=0.f,a11=0.f,a12=0.f,a13=0.f;
    #pragma unroll 4
    for(int j4=0;j4<128;j4++){
        float4 p0 = p0v[j4];
        float4 p1 = p1v[j4];
        const float* vb = Vp + j4*128 + lane;
        float v0 = vb[0], v1 = vb[32], v2 = vb[64], v3 = vb[96];
        a00 = fmaf(p0.x,v0,a00); a01 = fmaf(p0.y,v1,a01);
        a02 = fmaf(p0.z,v2,a02); a03 = fmaf(p0.w,v3,a03);
        a10 = fmaf(p1.x,v0,a10); a11 = fmaf(p1.y,v1,a11);
        a12 = fmaf(p1.z,v2,a12); a13 = fmaf(p1.w,v3,a13);
    }
    float a0 = (a00+a01)+(a02+a03);
    float a1 = (a10+a11)+(a12+a13);
    float wl = We[h*32 + lane], bl = be[h*32 + lane];
    out[((b*SN + i0)*NH + h)*HD + lane] = tfround(a0*inv0 + (sd0*inv0)*wl + bl);
    out[((b*SN + i1)*NH + h)*HD + lane] = tfround(a1*inv1 + (sd1*inv1)*wl + bl);
}

// ---------------- gate + residual, fused next-LN (l=0) or fused decode (l=1) ----------------
template<bool LAST>
__global__ void __launch_bounds__(256) k_gate(const float* __restrict__ o, const float* __restrict__ wg,
                                              float* __restrict__ nodes,
                                              const float* __restrict__ lng, const float* __restrict__ lnb,
                                              float* __restrict__ h,
                                              const float* __restrict__ Wd, float* __restrict__ out){
    int w = threadIdx.x >> 5, lane = threadIdx.x & 31;
    int tok = blockIdx.x*8 + w;
    const float* op = o + tok*DIM;
    float* np = nodes + tok*DIM;
    float ov[8], nv[8];
    float s = 0.f;
    #pragma unroll
    for(int k=0;k<8;k++){
        int c = lane + k*32;
        ov[k] = op[c]; nv[k] = np[c];
        s = fmaf(ov[k], wg[c] + wg[512+c], s);
        s = fmaf(nv[k], wg[256+c] - wg[512+c], s);
    }
    s = warpSum(s);
    float g = 1.f / (1.f + __expf(-s));
    float newv[8];
    float vs = 0.f;
    #pragma unroll
    for(int k=0;k<8;k++){
        newv[k] = ov[k]*g + nv[k]*(1.f - g);
        vs += newv[k];
    }
    if(!LAST){
        vs = warpSum(vs);
        float mean = vs * (1.f/DIM);
        float v2 = 0.f;
        #pragma unroll
        for(int k=0;k<8;k++){ float d = newv[k]-mean; v2 = fmaf(d,d,v2); }
        v2 = warpSum(v2);
        float rstd = rsqrtf(v2*(1.f/DIM) + 1e-5f);
        #pragma unroll
        for(int k=0;k<8;k++){
            int c = lane + k*32;
            np[c] = newv[k];
            h[tok*DIM + c] = tfround(fmaf((newv[k]-mean)*rstd, lng[c], lnb[c]));
        }
    } else {
        float a0 = 0.f, a1 = 0.f, a2 = 0.f;
        #pragma unroll
        for(int k=0;k<8;k++){
            int c = lane + k*32;
            a0 = fmaf(newv[k], Wd[c*3+0], a0);
            a1 = fmaf(newv[k], Wd[c*3+1], a1);
            a2 = fmaf(newv[k], Wd[c*3+2], a2);
        }
        a0 = warpSum(a0); a1 = warpSum(a1); a2 = warpSum(a2);
        if(lane == 0){
            out[tok*3+0] = a0; out[tok*3+1] = a1; out[tok*3+2] = a2;
        }
    }
}

// ---------------- launch ----------------
extern "C" void kernel_launch(void* const* d_in, const int* in_sizes, int n_in,
                              void* d_out, int out_size){
    (void)in_sizes; (void)n_in; (void)out_size;
    const float* x     = (const float*)d_in[0];
    const float* t     = (const float*)d_in[1];
    const float* W_enc = (const float*)d_in[2];
    const float* W_dec = (const float*)d_in[3];
    const float* ln_g  = (const float*)d_in[4];
    const float* ln_b  = (const float*)d_in[5];
    const float* Wq    = (const float*)d_in[6];
    const float* bq    = (const float*)d_in[7];
    const float* Wkv   = (const float*)d_in[8];
    const float* bkv   = (const float*)d_in[9];
    const float* We    = (const float*)d_in[10];
    const float* be    = (const float*)d_in[11];
    const float* Wo    = (const float*)d_in[12];
    const float* bo    = (const float*)d_in[13];
    const float* Wg    = (const float*)d_in[14];
    float* out = (float*)d_out;

    float *dist,*nodes,*h,*qkv,*q,*kt,*v,*qwe,*qbe,*attno,*ofull,*tab,*wq,*wkv,*wo;
    cudaGetSymbolAddress((void**)&dist,  g_dist);
    cudaGetSymbolAddress((void**)&nodes, g_nodes);
    cudaGetSymbolAddress((void**)&h,     g_h);
    cudaGetSymbolAddress((void**)&qkv,   g_qkv);
    cudaGetSymbolAddress((void**)&q,     g_q);
    cudaGetSymbolAddress((void**)&kt,    g_kt);
    cudaGetSymbolAddress((void**)&v,     g_v);
    cudaGetSymbolAddress((void**)&qwe,   g_qwe);
    cudaGetSymbolAddress((void**)&qbe,   g_qbe);
    cudaGetSymbolAddress((void**)&attno, g_attno);
    cudaGetSymbolAddress((void**)&ofull, g_out);
    cudaGetSymbolAddress((void**)&tab,   g_tab);
    cudaGetSymbolAddress((void**)&wq,    g_wq);
    cudaGetSymbolAddress((void**)&wkv,   g_wkv);
    cudaGetSymbolAddress((void**)&wo,    g_wo);

    const int gemm_smem = 3*(64*36 + 32*72)*4;   // 55296 bytes
    cudaFuncSetAttribute(k_gemm_tc<true>,  cudaFuncAttributeMaxDynamicSharedMemorySize, gemm_smem);
    cudaFuncSetAttribute(k_gemm_tc<false>, cudaFuncAttributeMaxDynamicSharedMemorySize, gemm_smem);

    // side stream: prep (needed by first GEMM) then dist (needed by first attn)
    cudaStream_t sB;
    cudaStreamCreateWithFlags(&sB, cudaStreamNonBlocking);
    cudaEvent_t eF, eP, eJ;
    cudaEventCreateWithFlags(&eF, cudaEventDisableTiming);
    cudaEventCreateWithFlags(&eP, cudaEventDisableTiming);
    cudaEventCreateWithFlags(&eJ, cudaEventDisableTiming);
    cudaEventRecord(eF, 0);
    cudaStreamWaitEvent(sB, eF, 0);
    k_prep<<<2080,256,0,sB>>>(Wq, Wkv, Wo, wq, wkv, wo, tab);
    cudaEventRecord(eP, sB);
    k_dist<<<2048,256,0,sB>>>(x, dist);
    cudaEventRecord(eJ, sB);

    k_encode<<<128,256>>>(x, t, W_enc, ln_g, ln_b, nodes, h);
    cudaStreamWaitEvent(0, eP, 0);

    for(int l=0;l<2;l++){
        k_gemm_tc<true><<<dim3(12,16),256,gemm_smem>>>(h, wq + l*DIM*DIM, bq + l*DIM,
                                            wkv + l*DIM*2*DIM, bkv + l*2*DIM, qkv);
        k_rot<<<1024,256>>>(qkv, We + l*DIM, be + l*DIM, tab, q, qwe, qbe, kt, v);
        if(l == 0) cudaStreamWaitEvent(0, eJ, 0);
        k_attn2<<<512,256>>>(q, kt, v, qwe, qbe, dist, We + l*DIM, be + l*DIM, attno);
        k_gemm_tc<false><<<dim3(4,16),256,gemm_smem>>>(attno, wo + l*DIM*DIM, bo + l*DIM,
                                            nullptr, nullptr, ofull);
        if(l == 0)
            k_gate<false><<<128,256>>>(ofull, Wg, nodes, ln_g + DIM, ln_b + DIM, h,
                                       nullptr, nullptr);
        else
            k_gate<true><<<128,256>>>(ofull, Wg + 3*DIM, nodes, nullptr, nullptr, nullptr,
                                      W_dec, out);
    }
}

// round 11
// speedup vs baseline: 1.1071x; 1.0666x over previous
#include <cuda_runtime.h>
#include <math.h>

#define NB 2
#define SN 512
#define DIM 256
#define NH 8
#define HD 32
#define QSCALE 0.17677669529663689f   // 1/sqrt(32)
#define FREQC  0.5756462732485115f    // ln(10000)/16

// ---------------- scratch (device globals) ----------------
__device__ __align__(256) float g_dist [NB*SN*SN];
__device__ __align__(256) float g_nodes[NB*SN*DIM];
__device__ __align__(256) float g_h    [NB*SN*DIM];
__device__ __align__(256) float g_q    [NB*NH*SN*HD];
__device__ __align__(256) float g_kt   [NB*NH*HD*SN];
__device__ __align__(256) float g_v    [NB*NH*SN*HD];
__device__ __align__(256) float g_qwe  [NB*NH*SN];
__device__ __align__(256) float g_qbe  [NB*NH*SN];
__device__ __align__(256) float g_attno[NB*SN*DIM];
__device__ __align__(256) float g_out  [NB*SN*DIM];
__device__ __align__(256) float g_tab  [SN*32];
__device__ __align__(256) float g_wq   [2*DIM*DIM];
__device__ __align__(256) float g_wkv  [2*DIM*2*DIM];
__device__ __align__(256) float g_wo   [2*DIM*DIM];

// ---------------- helpers ----------------
__device__ __forceinline__ float warpSum(float v){
    #pragma unroll
    for(int o=16;o;o>>=1) v += __shfl_xor_sync(0xffffffffu, v, o);
    return v;
}
__device__ __forceinline__ float warpMax(float v){
    #pragma unroll
    for(int o=16;o;o>>=1) v = fmaxf(v, __shfl_xor_sync(0xffffffffu, v, o));
    return v;
}
__device__ __forceinline__ unsigned f2tf(float f){
    unsigned r; asm("cvt.rna.tf32.f32 %0, %1;" : "=r"(r) : "f"(f)); return r;
}
__device__ __forceinline__ float tfround(float f){ return __uint_as_float(f2tf(f)); }
__device__ __forceinline__ void mma8(float* c, unsigned a0, unsigned a1, unsigned a2, unsigned a3,
                                     unsigned b0, unsigned b1){
    asm("mma.sync.aligned.m16n8k8.row.col.f32.tf32.tf32.f32 "
        "{%0,%1,%2,%3},{%4,%5,%6,%7},{%8,%9},{%0,%1,%2,%3};"
        : "+f"(c[0]),"+f"(c[1]),"+f"(c[2]),"+f"(c[3])
        : "r"(a0),"r"(a1),"r"(a2),"r"(a3),"r"(b0),"r"(b1));
}
__device__ __forceinline__ void cpa16(unsigned s, const void* g){
    asm volatile("cp.async.cg.shared.global [%0], [%1], 16;" :: "r"(s), "l"(g));
}

// ---------------- prep: trig table + weight tf32-rounding ----------------
__global__ void __launch_bounds__(256) k_prep(const float* __restrict__ Wq, const float* __restrict__ Wkv,
                                              const float* __restrict__ Wo,
                                              float* __restrict__ wq, float* __restrict__ wkv,
                                              float* __restrict__ wo, float* __restrict__ tab){
    int i = blockIdx.x*256 + threadIdx.x;          // < 532480
    if(i < 8192){
        int ii = i >> 4, fd = i & 15;
        float fr = (float)ii * expf(-(float)fd * FREQC);
        tab[ii*32 + fd]      = cosf(fr);
        tab[ii*32 + 16 + fd] = sinf(fr);
    }
    int j = i - 8192;
    if(j >= 0){
        if(j < 131072)       wq[j]         = tfround(Wq[j]);
        else if(j < 393216)  wkv[j-131072] = tfround(Wkv[j-131072]);
        else if(j < 524288)  wo[j-393216]  = tfround(Wo[j-393216]);
    }
}

// ---------------- pairwise distances ----------------
__global__ void __launch_bounds__(256) k_dist(const float* __restrict__ x, float* __restrict__ dist){
    int idx = blockIdx.x*256 + threadIdx.x;
    int j = idx & 511; int rest = idx >> 9;
    int i = rest & 511; int b = rest >> 9;
    const float* xi = x + (b*SN + i)*3;
    const float* xj = x + (b*SN + j)*3;
    float d0 = xi[0]-xj[0], d1 = xi[1]-xj[1], d2 = xi[2]-xj[2];
    float q = d0*d0 + d1*d1 + d2*d2;
    dist[idx] = (q > 0.f) ? sqrtf(q) : 0.f;
}

// ---------------- encoder + fused LN (warp per token) ----------------
__global__ void __launch_bounds__(256) k_encode(const float* __restrict__ x, const float* __restrict__ t,
                                                const float* __restrict__ W,
                                                const float* __restrict__ lng, const float* __restrict__ lnb,
                                                float* __restrict__ nodes, float* __restrict__ h){
    int w = threadIdx.x >> 5, lane = threadIdx.x & 31;
    int tok = blockIdx.x*8 + w;
    const float* xp = x + tok*3;
    float x0 = xp[0], x1 = xp[1], x2 = xp[2], tt = t[tok];
    float v[8]; float s = 0.f;
    #pragma unroll
    for(int k=0;k<8;k++){
        int c = lane + k*32;
        v[k] = x0*W[c] + x1*W[256+c] + x2*W[512+c] + tt*W[768+c];
        s += v[k];
    }
    s = warpSum(s);
    float mean = s * (1.f/DIM);
    float v2 = 0.f;
    #pragma unroll
    for(int k=0;k<8;k++){ float d = v[k]-mean; v2 = fmaf(d,d,v2); }
    v2 = warpSum(v2);
    float rstd = rsqrtf(v2*(1.f/DIM) + 1e-5f);
    #pragma unroll
    for(int k=0;k<8;k++){
        int c = lane + k*32;
        int idx = tok*DIM + c;
        nodes[idx] = v[k];
        h[idx] = tfround(fmaf((v[k]-mean)*rstd, lng[c], lnb[c]));
    }
}

// ============ tf32 GEMM: BM=64, BN=64, BK=32, NST=3, 8 warps (4x2), dyn smem ============
// QKV=true : grid (12,16); epilogue applies rotary and writes q/kt/v + qwe/qbe directly.
// QKV=false: grid (4,16);  plain C store.
template<bool QKV>
__global__ void __launch_bounds__(256) k_gemm_tc(const float* __restrict__ A,
        const float* __restrict__ W1, const float* __restrict__ b1,
        const float* __restrict__ W2, const float* __restrict__ b2,
        const float* __restrict__ We, const float* __restrict__ be,
        const float* __restrict__ tab,
        float* __restrict__ q, float* __restrict__ qwe, float* __restrict__ qbe,
        float* __restrict__ kt, float* __restrict__ v,
        float* __restrict__ C){
    constexpr int BM=64, BK=32, BN=64, K=256, NST=3;
    constexpr int AST = BK+4;        // 36
    constexpr int BSTR = BN+8;       // 72
    constexpr int ASZ = BM*AST;
    constexpr int BSZ = BK*BSTR;
    extern __shared__ float sm[];
    float* Asm = sm;
    float* Bsm = sm + NST*ASZ;

    int tx = threadIdx.x;
    int wid = tx>>5, lane = tx&31;
    int bcol = blockIdx.x*BN, brow = blockIdx.y*BM;

    const float* W; const float* bias; int ldb;
    if(QKV){
        if(bcol < 256){ W = W1 + bcol;        bias = b1 + bcol;        ldb = 256; }
        else          { W = W2 + (bcol-256);  bias = b2 + (bcol-256);  ldb = 512; }
    } else {            W = W1 + bcol;        bias = b1 + bcol;        ldb = 256; }

    int ar[2], ak4[2];
    #pragma unroll
    for(int u=0;u<2;u++){ int f = tx + u*256; ar[u]=f>>3; ak4[u]=(f&7)*4; }
    int br[2], bc4[2];
    #pragma unroll
    for(int u=0;u<2;u++){ int f = tx + u*256; br[u]=f>>4; bc4[u]=(f&15)*4; }

    const float* Ab = A + brow*K;
    unsigned sA = (unsigned)__cvta_generic_to_shared(Asm);
    unsigned sB = (unsigned)__cvta_generic_to_shared(Bsm);
    unsigned saoff[2], sboff[2];
    #pragma unroll
    for(int u=0;u<2;u++) saoff[u] = (ar[u]*AST + ak4[u])*4u;
    #pragma unroll
    for(int u=0;u<2;u++) sboff[u] = (br[u]*BSTR + bc4[u])*4u;
    const float* ga[2]; const float* gb[2];
    #pragma unroll
    for(int u=0;u<2;u++) ga[u] = Ab + ar[u]*K + ak4[u];
    #pragma unroll
    for(int u=0;u<2;u++) gb[u] = W + br[u]*ldb + bc4[u];

    const int NT = K/BK;   // 8
    #pragma unroll
    for(int s=0;s<2;s++){
        unsigned a0 = sA + s*ASZ*4u, b0 = sB + s*BSZ*4u;
        #pragma unroll
        for(int u=0;u<2;u++) cpa16(a0 + saoff[u], ga[u] + s*BK);
        #pragma unroll
        for(int u=0;u<2;u++) cpa16(b0 + sboff[u], gb[u] + s*BK*ldb);
        asm volatile("cp.async.commit_group;" ::: "memory");
    }

    int wm = (wid & 3)*16, wn = (wid >> 2)*32;
    float acc[4][4];
    #pragma unroll
    for(int nt=0;nt<4;nt++)
        #pragma unroll
        for(int e=0;e<4;e++) acc[nt][e] = 0.f;

    for(int t=0;t<NT;t++){
        asm volatile("cp.async.wait_group 1;" ::: "memory");
        __syncthreads();
        int lt = t+2;
        if(lt < NT){
            int slot = lt % NST;
            unsigned a0 = sA + slot*ASZ*4u, b0 = sB + slot*BSZ*4u;
            #pragma unroll
            for(int u=0;u<2;u++) cpa16(a0 + saoff[u], ga[u] + lt*BK);
            #pragma unroll
            for(int u=0;u<2;u++) cpa16(b0 + sboff[u], gb[u] + lt*BK*ldb);
        }
        asm volatile("cp.async.commit_group;" ::: "memory");

        const float* As_ = Asm + (t%NST)*ASZ;
        const float* Bs_ = Bsm + (t%NST)*BSZ;
        #pragma unroll
        for(int ks=0;ks<4;ks++){
            int kq = ks*8 + (lane&3);
            int arow = wm + (lane>>2);
            unsigned a0 = __float_as_uint(As_[ arow   *AST + kq  ]);
            unsigned a1 = __float_as_uint(As_[(arow+8)*AST + kq  ]);
            unsigned a2 = __float_as_uint(As_[ arow   *AST + kq+4]);
            unsigned a3 = __float_as_uint(As_[(arow+8)*AST + kq+4]);
            int bc0 = wn + (lane>>2);
            unsigned b[4][2];
            #pragma unroll
            for(int nt=0;nt<4;nt++){
                b[nt][0] = __float_as_uint(Bs_[ kq   *BSTR + bc0 + nt*8]);
                b[nt][1] = __float_as_uint(Bs_[(kq+4)*BSTR + bc0 + nt*8]);
            }
            #pragma unroll
            for(int nt=0;nt<4;nt++)
                mma8(acc[nt], a0,a1,a2,a3, b[nt][0],b[nt][1]);
        }
    }

    // ---------------- epilogue ----------------
    // bias-added values: vv[nt][e]; e0,e1 = row r cols c,c+1; e2,e3 = row r+8
    float vv[4][4];
    #pragma unroll
    for(int nt=0;nt<4;nt++){
        int lc = wn + nt*8 + (lane&3)*2;
        float bz0 = bias[lc], bz1 = bias[lc+1];
        vv[nt][0] = acc[nt][0] + bz0;  vv[nt][1] = acc[nt][1] + bz1;
        vv[nt][2] = acc[nt][2] + bz0;  vv[nt][3] = acc[nt][3] + bz1;
    }

    if(!QKV){
        int r = brow + wm + (lane>>2);
        #pragma unroll
        for(int nt=0;nt<4;nt++){
            int col = bcol + wn + nt*8 + (lane&3)*2;
            float* c0p = C + r*256 + col;
            c0p[0] = vv[nt][0]; c0p[1] = vv[nt][1];
            float* c1p = C + (r+8)*256 + col;
            c1p[0] = vv[nt][2]; c1p[1] = vv[nt][3];
        }
        return;
    }

    // QKV + rotary epilogue. Block column type: 0=q, 1=k, 2=v
    int btype = (bcol < 256) ? 0 : (bcol < 512 ? 1 : 2);
    int hloc;                                  // head index 0..7
    if(btype == 0)      hloc = (bcol + wn) >> 5;
    else if(btype == 1) hloc = (bcol - 256 + wn) >> 5;
    else                hloc = (bcol - 512 + wn) >> 5;

    #pragma unroll
    for(int rr=0;rr<2;rr++){
        int tokg = brow + wm + (lane>>2) + rr*8;
        int b = tokg >> 9, i = tokg & 511;
        int bh = b*NH + hloc;

        if(btype == 2){
            // V: plain relayout store (float2 per nt)
            float* vd = v + (bh*SN + i)*HD;
            #pragma unroll
            for(int nt=0;nt<4;nt++){
                int d = nt*8 + (lane&3)*2;
                *(float2*)(vd + d) = make_float2(vv[nt][rr*2], vv[nt][rr*2+1]);
            }
        } else {
            // rotary: partner of col d is d±16 = nt^2, same lane/e
            float dwe = 0.f, dbe = 0.f;
            #pragma unroll
            for(int nt=0;nt<4;nt++){
                int d0 = nt*8 + (lane&3)*2;
                float rv[2];
                #pragma unroll
                for(int e1=0;e1<2;e1++){
                    int d = d0 + e1, fd = d & 15;
                    float cs = tab[i*32 + fd];
                    float sn = tab[i*32 + 16 + fd];
                    float xv = vv[nt][rr*2+e1];
                    float xp = vv[nt^2][rr*2+e1];
                    float rot = (nt < 2) ? -xp : xp;
                    rv[e1] = xv*cs + rot*sn;
                }
                if(btype == 0){
                    rv[0] *= QSCALE; rv[1] *= QSCALE;
                    dwe = fmaf(rv[0], We[hloc*32 + d0    ], dwe);
                    dwe = fmaf(rv[1], We[hloc*32 + d0 + 1], dwe);
                    dbe = fmaf(rv[0], be[hloc*32 + d0    ], dbe);
                    dbe = fmaf(rv[1], be[hloc*32 + d0 + 1], dbe);
                    *(float2*)(q + (bh*SN + i)*HD + d0) = make_float2(rv[0], rv[1]);
                } else {
                    kt[(bh*HD + d0    )*SN + i] = rv[0];
                    kt[(bh*HD + d0 + 1)*SN + i] = rv[1];
                }
            }
            if(btype == 0){
                dwe += __shfl_xor_sync(0xffffffffu, dwe, 1);
                dwe += __shfl_xor_sync(0xffffffffu, dwe, 2);
                dbe += __shfl_xor_sync(0xffffffffu, dbe, 1);
                dbe += __shfl_xor_sync(0xffffffffu, dbe, 2);
                if((lane & 3) == 0){
                    qwe[bh*SN + i] = dwe;
                    qbe[bh*SN + i] = dbe;
                }
            }
        }
    }
}

// ---------------- attention: warp handles 2 query rows ----------------
__global__ void __launch_bounds__(256) k_attn2(
    const float* __restrict__ q, const float* __restrict__ kt, const float* __restrict__ v,
    const float* __restrict__ qwe, const float* __restrict__ qbe, const float* __restrict__ dist,
    const float* __restrict__ We, const float* __restrict__ be, float* __restrict__ out)
{
    __shared__ __align__(16) float sp[16][512];
    int w = threadIdx.x >> 5, lane = threadIdx.x & 31;
    int bh = blockIdx.x >> 5;
    int chunk = blockIdx.x & 31;
    int b = bh >> 3, h = bh & 7;
    int i0 = chunk*16 + w*2, i1 = i0 + 1;

    float qr0[32], qr1[32];
    {
        float qv0 = q[(bh*SN + i0)*HD + lane];
        float qv1 = q[(bh*SN + i1)*HD + lane];
        #pragma unroll
        for(int d=0;d<32;d++){ qr0[d] = __shfl_sync(0xffffffffu, qv0, d);
                               qr1[d] = __shfl_sync(0xffffffffu, qv1, d); }
    }
    float cwe0 = qwe[bh*SN + i0], cwe1 = qwe[bh*SN + i1];
    float cbe0 = qbe[bh*SN + i0], cbe1 = qbe[bh*SN + i1];
    const float* Kt = kt + bh*HD*SN;
    const float* D0 = dist + (b*SN + i0)*SN;
    const float* D1 = dist + (b*SN + i1)*SN;

    float m0 = -1e30f, m1 = -1e30f;
    #pragma unroll
    for(int cb=0;cb<4;cb++){
        int j0 = cb*128 + lane*4;
        float4 s0 = make_float4(cbe0,cbe0,cbe0,cbe0);
        float4 s1 = make_float4(cbe1,cbe1,cbe1,cbe1);
        #pragma unroll
        for(int d=0;d<32;d++){
            float4 kk = *(const float4*)(Kt + d*SN + j0);
            s0.x = fmaf(qr0[d], kk.x, s0.x); s0.y = fmaf(qr0[d], kk.y, s0.y);
            s0.z = fmaf(qr0[d], kk.z, s0.z); s0.w = fmaf(qr0[d], kk.w, s0.w);
            s1.x = fmaf(qr1[d], kk.x, s1.x); s1.y = fmaf(qr1[d], kk.y, s1.y);
            s1.z = fmaf(qr1[d], kk.z, s1.z); s1.w = fmaf(qr1[d], kk.w, s1.w);
        }
        float4 d0 = *(const float4*)(D0 + j0);
        float4 d1 = *(const float4*)(D1 + j0);
        s0.x = fmaf(d0.x, cwe0, s0.x); s0.y = fmaf(d0.y, cwe0, s0.y);
        s0.z = fmaf(d0.z, cwe0, s0.z); s0.w = fmaf(d0.w, cwe0, s0.w);
        s1.x = fmaf(d1.x, cwe1, s1.x); s1.y = fmaf(d1.y, cwe1, s1.y);
        s1.z = fmaf(d1.z, cwe1, s1.z); s1.w = fmaf(d1.w, cwe1, s1.w);
        *(float4*)&sp[w*2  ][j0] = s0;
        *(float4*)&sp[w*2+1][j0] = s1;
        m0 = fmaxf(m0, fmaxf(fmaxf(s0.x,s0.y), fmaxf(s0.z,s0.w)));
        m1 = fmaxf(m1, fmaxf(fmaxf(s1.x,s1.y), fmaxf(s1.z,s1.w)));
    }
    m0 = warpMax(m0); m1 = warpMax(m1);

    float sum0 = 0.f, sum1 = 0.f, sd0 = 0.f, sd1 = 0.f;
    #pragma unroll
    for(int cb=0;cb<4;cb++){
        int j0 = cb*128 + lane*4;
        float4 s0 = *(const float4*)&sp[w*2  ][j0];
        float4 s1 = *(const float4*)&sp[w*2+1][j0];
        float4 d0 = *(const float4*)(D0 + j0);
        float4 d1 = *(const float4*)(D1 + j0);
        float4 p0, p1;
        p0.x = __expf(s0.x-m0); p0.y = __expf(s0.y-m0); p0.z = __expf(s0.z-m0); p0.w = __expf(s0.w-m0);
        p1.x = __expf(s1.x-m1); p1.y = __expf(s1.y-m1); p1.z = __expf(s1.z-m1); p1.w = __expf(s1.w-m1);
        sum0 += (p0.x+p0.y)+(p0.z+p0.w);
        sum1 += (p1.x+p1.y)+(p1.z+p1.w);
        sd0 = fmaf(p0.x,d0.x,sd0); sd0 = fmaf(p0.y,d0.y,sd0); sd0 = fmaf(p0.z,d0.z,sd0); sd0 = fmaf(p0.w,d0.w,sd0);
        sd1 = fmaf(p1.x,d1.x,sd1); sd1 = fmaf(p1.y,d1.y,sd1); sd1 = fmaf(p1.z,d1.z,sd1); sd1 = fmaf(p1.w,d1.w,sd1);
        *(float4*)&sp[w*2  ][j0] = p0;
        *(float4*)&sp[w*2+1][j0] = p1;
    }
    sum0 = warpSum(sum0); sum1 = warpSum(sum1);
    sd0  = warpSum(sd0);  sd1  = warpSum(sd1);
    float inv0 = 1.f/sum0, inv1 = 1.f/sum1;
    __syncwarp();

    const float* Vp = v + bh*SN*HD;
    const float4* p0v = (const float4*)sp[w*2];
    const float4* p1v = (const float4*)sp[w*2+1];
    float a00=0.f,a01=0.f,a02=0.f,a03=0.f;
    float a10=0.f,a11=0.f,a12=0.f,a13=0.f;
    #pragma unroll 4
    for(int j4=0;j4<128;j4++){
        float4 p0 = p0v[j4];
        float4 p1 = p1v[j4];
        const float* vb = Vp + j4*128 + lane;
        float v0 = vb[0], v1 = vb[32], v2 = vb[64], v3 = vb[96];
        a00 = fmaf(p0.x,v0,a00); a01 = fmaf(p0.y,v1,a01);
        a02 = fmaf(p0.z,v2,a02); a03 = fmaf(p0.w,v3,a03);
        a10 = fmaf(p1.x,v0,a10); a11 = fmaf(p1.y,v1,a11);
        a12 = fmaf(p1.z,v2,a12); a13 = fmaf(p1.w,v3,a13);
    }
    float a0 = (a00+a01)+(a02+a03);
    float a1 = (a10+a11)+(a12+a13);
    float wl = We[h*32 + lane], bl = be[h*32 + lane];
    out[((b*SN + i0)*NH + h)*HD + lane] = tfround(a0*inv0 + (sd0*inv0)*wl + bl);
    out[((b*SN + i1)*NH + h)*HD + lane] = tfround(a1*inv1 + (sd1*inv1)*wl + bl);
}

// ---------------- gate + residual, fused next-LN (l=0) or fused decode (l=1) ----------------
template<bool LAST>
__global__ void __launch_bounds__(256) k_gate(const float* __restrict__ o, const float* __restrict__ wg,
                                              float* __restrict__ nodes,
                                              const float* __restrict__ lng, const float* __restrict__ lnb,
                                              float* __restrict__ h,
                                              const float* __restrict__ Wd, float* __restrict__ out){
    int w = threadIdx.x >> 5, lane = threadIdx.x & 31;
    int tok = blockIdx.x*8 + w;
    const float* op = o + tok*DIM;
    float* np = nodes + tok*DIM;
    float ov[8], nv[8];
    float s = 0.f;
    #pragma unroll
    for(int k=0;k<8;k++){
        int c = lane + k*32;
        ov[k] = op[c]; nv[k] = np[c];
        s = fmaf(ov[k], wg[c] + wg[512+c], s);
        s = fmaf(nv[k], wg[256+c] - wg[512+c], s);
    }
    s = warpSum(s);
    float g = 1.f / (1.f + __expf(-s));
    float newv[8];
    float vs = 0.f;
    #pragma unroll
    for(int k=0;k<8;k++){
        newv[k] = ov[k]*g + nv[k]*(1.f - g);
        vs += newv[k];
    }
    if(!LAST){
        vs = warpSum(vs);
        float mean = vs * (1.f/DIM);
        float v2 = 0.f;
        #pragma unroll
        for(int k=0;k<8;k++){ float d = newv[k]-mean; v2 = fmaf(d,d,v2); }
        v2 = warpSum(v2);
        float rstd = rsqrtf(v2*(1.f/DIM) + 1e-5f);
        #pragma unroll
        for(int k=0;k<8;k++){
            int c = lane + k*32;
            np[c] = newv[k];
            h[tok*DIM + c] = tfround(fmaf((newv[k]-mean)*rstd, lng[c], lnb[c]));
        }
    } else {
        float a0 = 0.f, a1 = 0.f, a2 = 0.f;
        #pragma unroll
        for(int k=0;k<8;k++){
            int c = lane + k*32;
            a0 = fmaf(newv[k], Wd[c*3+0], a0);
            a1 = fmaf(newv[k], Wd[c*3+1], a1);
            a2 = fmaf(newv[k], Wd[c*3+2], a2);
        }
        a0 = warpSum(a0); a1 = warpSum(a1); a2 = warpSum(a2);
        if(lane == 0){
            out[tok*3+0] = a0; out[tok*3+1] = a1; out[tok*3+2] = a2;
        }
    }
}

// ---------------- launch ----------------
extern "C" void kernel_launch(void* const* d_in, const int* in_sizes, int n_in,
                              void* d_out, int out_size){
    (void)in_sizes; (void)n_in; (void)out_size;
    const float* x     = (const float*)d_in[0];
    const float* t     = (const float*)d_in[1];
    const float* W_enc = (const float*)d_in[2];
    const float* W_dec = (const float*)d_in[3];
    const float* ln_g  = (const float*)d_in[4];
    const float* ln_b  = (const float*)d_in[5];
    const float* Wq    = (const float*)d_in[6];
    const float* bq    = (const float*)d_in[7];
    const float* Wkv   = (const float*)d_in[8];
    const float* bkv   = (const float*)d_in[9];
    const float* We    = (const float*)d_in[10];
    const float* be    = (const float*)d_in[11];
    const float* Wo    = (const float*)d_in[12];
    const float* bo    = (const float*)d_in[13];
    const float* Wg    = (const float*)d_in[14];
    float* out = (float*)d_out;

    float *dist,*nodes,*h,*q,*kt,*v,*qwe,*qbe,*attno,*ofull,*tab,*wq,*wkv,*wo;
    cudaGetSymbolAddress((void**)&dist,  g_dist);
    cudaGetSymbolAddress((void**)&nodes, g_nodes);
    cudaGetSymbolAddress((void**)&h,     g_h);
    cudaGetSymbolAddress((void**)&q,     g_q);
    cudaGetSymbolAddress((void**)&kt,    g_kt);
    cudaGetSymbolAddress((void**)&v,     g_v);
    cudaGetSymbolAddress((void**)&qwe,   g_qwe);
    cudaGetSymbolAddress((void**)&qbe,   g_qbe);
    cudaGetSymbolAddress((void**)&attno, g_attno);
    cudaGetSymbolAddress((void**)&ofull, g_out);
    cudaGetSymbolAddress((void**)&tab,   g_tab);
    cudaGetSymbolAddress((void**)&wq,    g_wq);
    cudaGetSymbolAddress((void**)&wkv,   g_wkv);
    cudaGetSymbolAddress((void**)&wo,    g_wo);

    const int gemm_smem = 3*(64*36 + 32*72)*4;   // 55296 bytes
    cudaFuncSetAttribute(k_gemm_tc<true>,  cudaFuncAttributeMaxDynamicSharedMemorySize, gemm_smem);
    cudaFuncSetAttribute(k_gemm_tc<false>, cudaFuncAttributeMaxDynamicSharedMemorySize, gemm_smem);

    // side stream: prep (needed by first GEMM) then dist (needed by first attn)
    cudaStream_t sB;
    cudaStreamCreateWithFlags(&sB, cudaStreamNonBlocking);
    cudaEvent_t eF, eP, eJ;
    cudaEventCreateWithFlags(&eF, cudaEventDisableTiming);
    cudaEventCreateWithFlags(&eP, cudaEventDisableTiming);
    cudaEventCreateWithFlags(&eJ, cudaEventDisableTiming);
    cudaEventRecord(eF, 0);
    cudaStreamWaitEvent(sB, eF, 0);
    k_prep<<<2080,256,0,sB>>>(Wq, Wkv, Wo, wq, wkv, wo, tab);
    cudaEventRecord(eP, sB);
    k_dist<<<2048,256,0,sB>>>(x, dist);
    cudaEventRecord(eJ, sB);

    k_encode<<<128,256>>>(x, t, W_enc, ln_g, ln_b, nodes, h);
    cudaStreamWaitEvent(0, eP, 0);

    for(int l=0;l<2;l++){
        k_gemm_tc<true><<<dim3(12,16),256,gemm_smem>>>(h,
            wq + l*DIM*DIM, bq + l*DIM, wkv + l*DIM*2*DIM, bkv + l*2*DIM,
            We + l*DIM, be + l*DIM, tab, q, qwe, qbe, kt, v, nullptr);
        if(l == 0) cudaStreamWaitEvent(0, eJ, 0);
        k_attn2<<<512,256>>>(q, kt, v, qwe, qbe, dist, We + l*DIM, be + l*DIM, attno);
        k_gemm_tc<false><<<dim3(4,16),256,gemm_smem>>>(attno,
            wo + l*DIM*DIM, bo + l*DIM, nullptr, nullptr,
            nullptr, nullptr, nullptr, nullptr, nullptr, nullptr, nullptr, nullptr, ofull);
        if(l == 0)
            k_gate<false><<<128,256>>>(ofull, Wg, nodes, ln_g + DIM, ln_b + DIM, h,
                                       nullptr, nullptr);
        else
            k_gate<true><<<128,256>>>(ofull, Wg + 3*DIM, nodes, nullptr, nullptr, nullptr,
                                      W_dec, out);
    }
}

// round 12
// speedup vs baseline: 1.1234x; 1.0148x over previous
#include <cuda_runtime.h>
#include <math.h>

#define NB 2
#define SN 512
#define DIM 256
#define NH 8
#define HD 32
#define QSCALE 0.17677669529663689f   // 1/sqrt(32)
#define FREQC  0.5756462732485115f    // ln(10000)/16
#define SPST 520                      // sim smem row stride (pad 8)

// ---------------- scratch (device globals) ----------------
__device__ __align__(256) float g_dist [NB*SN*SN];
__device__ __align__(256) float g_nodes[NB*SN*DIM];
__device__ __align__(256) float g_h    [NB*SN*DIM];
__device__ __align__(256) float g_q    [NB*NH*SN*HD];
__device__ __align__(256) float g_kt   [NB*NH*HD*SN];
__device__ __align__(256) float g_v    [NB*NH*SN*HD];
__device__ __align__(256) float g_qwe  [NB*NH*SN];
__device__ __align__(256) float g_qbe  [NB*NH*SN];
__device__ __align__(256) float g_attno[NB*SN*DIM];
__device__ __align__(256) float g_out  [NB*SN*DIM];
__device__ __align__(256) float g_tab  [SN*32];
__device__ __align__(256) float g_wq   [2*DIM*DIM];
__device__ __align__(256) float g_wkv  [2*DIM*2*DIM];
__device__ __align__(256) float g_wo   [2*DIM*DIM];

// ---------------- helpers ----------------
__device__ __forceinline__ float warpSum(float v){
    #pragma unroll
    for(int o=16;o;o>>=1) v += __shfl_xor_sync(0xffffffffu, v, o);
    return v;
}
__device__ __forceinline__ float warpMax(float v){
    #pragma unroll
    for(int o=16;o;o>>=1) v = fmaxf(v, __shfl_xor_sync(0xffffffffu, v, o));
    return v;
}
__device__ __forceinline__ unsigned f2tf(float f){
    unsigned r; asm("cvt.rna.tf32.f32 %0, %1;" : "=r"(r) : "f"(f)); return r;
}
__device__ __forceinline__ float tfround(float f){ return __uint_as_float(f2tf(f)); }
__device__ __forceinline__ void mma8(float* c, unsigned a0, unsigned a1, unsigned a2, unsigned a3,
                                     unsigned b0, unsigned b1){
    asm("mma.sync.aligned.m16n8k8.row.col.f32.tf32.tf32.f32 "
        "{%0,%1,%2,%3},{%4,%5,%6,%7},{%8,%9},{%0,%1,%2,%3};"
        : "+f"(c[0]),"+f"(c[1]),"+f"(c[2]),"+f"(c[3])
        : "r"(a0),"r"(a1),"r"(a2),"r"(a3),"r"(b0),"r"(b1));
}
__device__ __forceinline__ void cpa16(unsigned s, const void* g){
    asm volatile("cp.async.cg.shared.global [%0], [%1], 16;" :: "r"(s), "l"(g));
}

// ---------------- prep: trig table + weight tf32-rounding ----------------
__global__ void __launch_bounds__(256) k_prep(const float* __restrict__ Wq, const float* __restrict__ Wkv,
                                              const float* __restrict__ Wo,
                                              float* __restrict__ wq, float* __restrict__ wkv,
                                              float* __restrict__ wo, float* __restrict__ tab){
    int i = blockIdx.x*256 + threadIdx.x;
    if(i < 8192){
        int ii = i >> 4, fd = i & 15;
        float fr = (float)ii * expf(-(float)fd * FREQC);
        tab[ii*32 + fd]      = cosf(fr);
        tab[ii*32 + 16 + fd] = sinf(fr);
    }
    int j = i - 8192;
    if(j >= 0){
        if(j < 131072)       wq[j]         = tfround(Wq[j]);
        else if(j < 393216)  wkv[j-131072] = tfround(Wkv[j-131072]);
        else if(j < 524288)  wo[j-393216]  = tfround(Wo[j-393216]);
    }
}

// ---------------- pairwise distances ----------------
__global__ void __launch_bounds__(256) k_dist(const float* __restrict__ x, float* __restrict__ dist){
    int idx = blockIdx.x*256 + threadIdx.x;
    int j = idx & 511; int rest = idx >> 9;
    int i = rest & 511; int b = rest >> 9;
    const float* xi = x + (b*SN + i)*3;
    const float* xj = x + (b*SN + j)*3;
    float d0 = xi[0]-xj[0], d1 = xi[1]-xj[1], d2 = xi[2]-xj[2];
    float q = d0*d0 + d1*d1 + d2*d2;
    dist[idx] = (q > 0.f) ? sqrtf(q) : 0.f;
}

// ---------------- encoder + fused LN (warp per token) ----------------
__global__ void __launch_bounds__(256) k_encode(const float* __restrict__ x, const float* __restrict__ t,
                                                const float* __restrict__ W,
                                                const float* __restrict__ lng, const float* __restrict__ lnb,
                                                float* __restrict__ nodes, float* __restrict__ h){
    int w = threadIdx.x >> 5, lane = threadIdx.x & 31;
    int tok = blockIdx.x*8 + w;
    const float* xp = x + tok*3;
    float x0 = xp[0], x1 = xp[1], x2 = xp[2], tt = t[tok];
    float v[8]; float s = 0.f;
    #pragma unroll
    for(int k=0;k<8;k++){
        int c = lane + k*32;
        v[k] = x0*W[c] + x1*W[256+c] + x2*W[512+c] + tt*W[768+c];
        s += v[k];
    }
    s = warpSum(s);
    float mean = s * (1.f/DIM);
    float v2 = 0.f;
    #pragma unroll
    for(int k=0;k<8;k++){ float d = v[k]-mean; v2 = fmaf(d,d,v2); }
    v2 = warpSum(v2);
    float rstd = rsqrtf(v2*(1.f/DIM) + 1e-5f);
    #pragma unroll
    for(int k=0;k<8;k++){
        int c = lane + k*32;
        int idx = tok*DIM + c;
        nodes[idx] = v[k];
        h[idx] = tfround(fmaf((v[k]-mean)*rstd, lng[c], lnb[c]));
    }
}

// ============ tf32 GEMM: BM=64, BN=64, BK=32, NST=3, 8 warps (4x2), dyn smem ============
// QKV=true : grid (12,16); epilogue applies rotary, tf32-rounds q/kt, writes q/kt/v + qwe/qbe.
// QKV=false: grid (4,16);  plain C store.
template<bool QKV>
__global__ void __launch_bounds__(256) k_gemm_tc(const float* __restrict__ A,
        const float* __restrict__ W1, const float* __restrict__ b1,
        const float* __restrict__ W2, const float* __restrict__ b2,
        const float* __restrict__ We, const float* __restrict__ be,
        const float* __restrict__ tab,
        float* __restrict__ q, float* __restrict__ qwe, float* __restrict__ qbe,
        float* __restrict__ kt, float* __restrict__ v,
        float* __restrict__ C){
    constexpr int BM=64, BK=32, BN=64, K=256, NST=3;
    constexpr int AST = BK+4;
    constexpr int BSTR = BN+8;
    constexpr int ASZ = BM*AST;
    constexpr int BSZ = BK*BSTR;
    extern __shared__ float sm[];
    float* Asm = sm;
    float* Bsm = sm + NST*ASZ;

    int tx = threadIdx.x;
    int wid = tx>>5, lane = tx&31;
    int bcol = blockIdx.x*BN, brow = blockIdx.y*BM;

    const float* W; const float* bias; int ldb;
    if(QKV){
        if(bcol < 256){ W = W1 + bcol;        bias = b1 + bcol;        ldb = 256; }
        else          { W = W2 + (bcol-256);  bias = b2 + (bcol-256);  ldb = 512; }
    } else {            W = W1 + bcol;        bias = b1 + bcol;        ldb = 256; }

    int ar[2], ak4[2];
    #pragma unroll
    for(int u=0;u<2;u++){ int f = tx + u*256; ar[u]=f>>3; ak4[u]=(f&7)*4; }
    int br[2], bc4[2];
    #pragma unroll
    for(int u=0;u<2;u++){ int f = tx + u*256; br[u]=f>>4; bc4[u]=(f&15)*4; }

    const float* Ab = A + brow*K;
    unsigned sA = (unsigned)__cvta_generic_to_shared(Asm);
    unsigned sB = (unsigned)__cvta_generic_to_shared(Bsm);
    unsigned saoff[2], sboff[2];
    #pragma unroll
    for(int u=0;u<2;u++) saoff[u] = (ar[u]*AST + ak4[u])*4u;
    #pragma unroll
    for(int u=0;u<2;u++) sboff[u] = (br[u]*BSTR + bc4[u])*4u;
    const float* ga[2]; const float* gb[2];
    #pragma unroll
    for(int u=0;u<2;u++) ga[u] = Ab + ar[u]*K + ak4[u];
    #pragma unroll
    for(int u=0;u<2;u++) gb[u] = W + br[u]*ldb + bc4[u];

    const int NT = K/BK;   // 8
    #pragma unroll
    for(int s=0;s<2;s++){
        unsigned a0 = sA + s*ASZ*4u, b0 = sB + s*BSZ*4u;
        #pragma unroll
        for(int u=0;u<2;u++) cpa16(a0 + saoff[u], ga[u] + s*BK);
        #pragma unroll
        for(int u=0;u<2;u++) cpa16(b0 + sboff[u], gb[u] + s*BK*ldb);
        asm volatile("cp.async.commit_group;" ::: "memory");
    }

    int wm = (wid & 3)*16, wn = (wid >> 2)*32;
    float acc[4][4];
    #pragma unroll
    for(int nt=0;nt<4;nt++)
        #pragma unroll
        for(int e=0;e<4;e++) acc[nt][e] = 0.f;

    for(int t=0;t<NT;t++){
        asm volatile("cp.async.wait_group 1;" ::: "memory");
        __syncthreads();
        int lt = t+2;
        if(lt < NT){
            int slot = lt % NST;
            unsigned a0 = sA + slot*ASZ*4u, b0 = sB + slot*BSZ*4u;
            #pragma unroll
            for(int u=0;u<2;u++) cpa16(a0 + saoff[u], ga[u] + lt*BK);
            #pragma unroll
            for(int u=0;u<2;u++) cpa16(b0 + sboff[u], gb[u] + lt*BK*ldb);
        }
        asm volatile("cp.async.commit_group;" ::: "memory");

        const float* As_ = Asm + (t%NST)*ASZ;
        const float* Bs_ = Bsm + (t%NST)*BSZ;
        #pragma unroll
        for(int ks=0;ks<4;ks++){
            int kq = ks*8 + (lane&3);
            int arow = wm + (lane>>2);
            unsigned a0 = __float_as_uint(As_[ arow   *AST + kq  ]);
            unsigned a1 = __float_as_uint(As_[(arow+8)*AST + kq  ]);
            unsigned a2 = __float_as_uint(As_[ arow   *AST + kq+4]);
            unsigned a3 = __float_as_uint(As_[(arow+8)*AST + kq+4]);
            int bc0 = wn + (lane>>2);
            unsigned b[4][2];
            #pragma unroll
            for(int nt=0;nt<4;nt++){
                b[nt][0] = __float_as_uint(Bs_[ kq   *BSTR + bc0 + nt*8]);
                b[nt][1] = __float_as_uint(Bs_[(kq+4)*BSTR + bc0 + nt*8]);
            }
            #pragma unroll
            for(int nt=0;nt<4;nt++)
                mma8(acc[nt], a0,a1,a2,a3, b[nt][0],b[nt][1]);
        }
    }

    // ---------------- epilogue ----------------
    float vv[4][4];
    #pragma unroll
    for(int nt=0;nt<4;nt++){
        int lc = wn + nt*8 + (lane&3)*2;
        float bz0 = bias[lc], bz1 = bias[lc+1];
        vv[nt][0] = acc[nt][0] + bz0;  vv[nt][1] = acc[nt][1] + bz1;
        vv[nt][2] = acc[nt][2] + bz0;  vv[nt][3] = acc[nt][3] + bz1;
    }

    if(!QKV){
        int r = brow + wm + (lane>>2);
        #pragma unroll
        for(int nt=0;nt<4;nt++){
            int col = bcol + wn + nt*8 + (lane&3)*2;
            float* c0p = C + r*256 + col;
            c0p[0] = vv[nt][0]; c0p[1] = vv[nt][1];
            float* c1p = C + (r+8)*256 + col;
            c1p[0] = vv[nt][2]; c1p[1] = vv[nt][3];
        }
        return;
    }

    int btype = (bcol < 256) ? 0 : (bcol < 512 ? 1 : 2);
    int hloc;
    if(btype == 0)      hloc = (bcol + wn) >> 5;
    else if(btype == 1) hloc = (bcol - 256 + wn) >> 5;
    else                hloc = (bcol - 512 + wn) >> 5;

    #pragma unroll
    for(int rr=0;rr<2;rr++){
        int tokg = brow + wm + (lane>>2) + rr*8;
        int b = tokg >> 9, i = tokg & 511;
        int bh = b*NH + hloc;

        if(btype == 2){
            float* vd = v + (bh*SN + i)*HD;
            #pragma unroll
            for(int nt=0;nt<4;nt++){
                int d = nt*8 + (lane&3)*2;
                *(float2*)(vd + d) = make_float2(vv[nt][rr*2], vv[nt][rr*2+1]);
            }
        } else {
            float dwe = 0.f, dbe = 0.f;
            #pragma unroll
            for(int nt=0;nt<4;nt++){
                int d0 = nt*8 + (lane&3)*2;
                float rv[2];
                #pragma unroll
                for(int e1=0;e1<2;e1++){
                    int d = d0 + e1, fd = d & 15;
                    float cs = tab[i*32 + fd];
                    float sn = tab[i*32 + 16 + fd];
                    float xv = vv[nt][rr*2+e1];
                    float xp = vv[nt^2][rr*2+e1];
                    float rot = (nt < 2) ? -xp : xp;
                    rv[e1] = xv*cs + rot*sn;
                }
                if(btype == 0){
                    rv[0] = tfround(rv[0]*QSCALE); rv[1] = tfround(rv[1]*QSCALE);
                    dwe = fmaf(rv[0], We[hloc*32 + d0    ], dwe);
                    dwe = fmaf(rv[1], We[hloc*32 + d0 + 1], dwe);
                    dbe = fmaf(rv[0], be[hloc*32 + d0    ], dbe);
                    dbe = fmaf(rv[1], be[hloc*32 + d0 + 1], dbe);
                    *(float2*)(q + (bh*SN + i)*HD + d0) = make_float2(rv[0], rv[1]);
                } else {
                    kt[(bh*HD + d0    )*SN + i] = tfround(rv[0]);
                    kt[(bh*HD + d0 + 1)*SN + i] = tfround(rv[1]);
                }
            }
            if(btype == 0){
                dwe += __shfl_xor_sync(0xffffffffu, dwe, 1);
                dwe += __shfl_xor_sync(0xffffffffu, dwe, 2);
                dbe += __shfl_xor_sync(0xffffffffu, dbe, 1);
                dbe += __shfl_xor_sync(0xffffffffu, dbe, 2);
                if((lane & 3) == 0){
                    qwe[bh*SN + i] = dwe;
                    qbe[bh*SN + i] = dbe;
                }
            }
        }
    }
}

// ---------------- attention: mma QK^T (block 16 rows), fp32 softmax + PV ----------------
__global__ void __launch_bounds__(256) k_attn2(
    const float* __restrict__ q, const float* __restrict__ kt, const float* __restrict__ v,
    const float* __restrict__ qwe, const float* __restrict__ qbe, const float* __restrict__ dist,
    const float* __restrict__ We, const float* __restrict__ be, float* __restrict__ out)
{
    __shared__ __align__(16) float sp[16][SPST];
    int w = threadIdx.x >> 5, lane = threadIdx.x & 31;
    int bh = blockIdx.x >> 5;
    int chunk = blockIdx.x & 31;
    int b = bh >> 3, h = bh & 7;
    int i0base = chunk*16;

    // ---- pass 1: sim[16][512] via tf32 mma; warp w covers cols [w*64, w*64+64) ----
    {
        int rql = lane >> 2;
        const float* Q = q + (bh*SN + i0base)*HD;
        unsigned a[4][4];
        #pragma unroll
        for(int kc=0;kc<4;kc++){
            int kq = kc*8 + (lane&3);
            a[kc][0] = __float_as_uint(Q[ rql   *HD + kq  ]);
            a[kc][1] = __float_as_uint(Q[(rql+8)*HD + kq  ]);
            a[kc][2] = __float_as_uint(Q[ rql   *HD + kq+4]);
            a[kc][3] = __float_as_uint(Q[(rql+8)*HD + kq+4]);
        }
        float acc[8][4];
        #pragma unroll
        for(int nt=0;nt<8;nt++){ acc[nt][0]=0.f; acc[nt][1]=0.f; acc[nt][2]=0.f; acc[nt][3]=0.f; }
        const float* Kt = kt + bh*HD*SN;
        int wn2 = w*64;
        #pragma unroll
        for(int kc=0;kc<4;kc++){
            int kq = kc*8 + (lane&3);
            const float* k0 = Kt + kq*SN;
            const float* k4 = Kt + (kq+4)*SN;
            #pragma unroll
            for(int nt=0;nt<8;nt++){
                int j = wn2 + nt*8 + rql;
                mma8(acc[nt], a[kc][0],a[kc][1],a[kc][2],a[kc][3],
                     __float_as_uint(k0[j]), __float_as_uint(k4[j]));
            }
        }
        int r0 = i0base + rql, r1 = r0 + 8;
        float cwe0 = qwe[bh*SN + r0], cbe0 = qbe[bh*SN + r0];
        float cwe1 = qwe[bh*SN + r1], cbe1 = qbe[bh*SN + r1];
        const float* Dr0 = dist + (b*SN + r0)*SN;
        const float* Dr1 = dist + (b*SN + r1)*SN;
        #pragma unroll
        for(int nt=0;nt<8;nt++){
            int c = wn2 + nt*8 + (lane&3)*2;
            float2 dd0 = *(const float2*)(Dr0 + c);
            float2 dd1 = *(const float2*)(Dr1 + c);
            sp[rql  ][c  ] = fmaf(dd0.x, cwe0, acc[nt][0] + cbe0);
            sp[rql  ][c+1] = fmaf(dd0.y, cwe0, acc[nt][1] + cbe0);
            sp[rql+8][c  ] = fmaf(dd1.x, cwe1, acc[nt][2] + cbe1);
            sp[rql+8][c+1] = fmaf(dd1.y, cwe1, acc[nt][3] + cbe1);
        }
    }
    __syncthreads();

    // ---- softmax: warp w owns rows 2w, 2w+1 ----
    int i0 = i0base + w*2, i1 = i0 + 1;
    float* sp0 = sp[w*2];
    float* sp1 = sp[w*2+1];
    const float* D0 = dist + (b*SN + i0)*SN;
    const float* D1 = dist + (b*SN + i1)*SN;

    float m0 = -1e30f, m1 = -1e30f;
    #pragma unroll
    for(int cb=0;cb<4;cb++){
        int j0 = cb*128 + lane*4;
        float4 s0 = *(const float4*)(sp0 + j0);
        float4 s1 = *(const float4*)(sp1 + j0);
        m0 = fmaxf(m0, fmaxf(fmaxf(s0.x,s0.y), fmaxf(s0.z,s0.w)));
        m1 = fmaxf(m1, fmaxf(fmaxf(s1.x,s1.y), fmaxf(s1.z,s1.w)));
    }
    m0 = warpMax(m0); m1 = warpMax(m1);

    float sum0 = 0.f, sum1 = 0.f, sd0 = 0.f, sd1 = 0.f;
    #pragma unroll
    for(int cb=0;cb<4;cb++){
        int j0 = cb*128 + lane*4;
        float4 s0 = *(const float4*)(sp0 + j0);
        float4 s1 = *(const float4*)(sp1 + j0);
        float4 d0 = *(const float4*)(D0 + j0);
        float4 d1 = *(const float4*)(D1 + j0);
        float4 p0, p1;
        p0.x = __expf(s0.x-m0); p0.y = __expf(s0.y-m0); p0.z = __expf(s0.z-m0); p0.w = __expf(s0.w-m0);
        p1.x = __expf(s1.x-m1); p1.y = __expf(s1.y-m1); p1.z = __expf(s1.z-m1); p1.w = __expf(s1.w-m1);
        sum0 += (p0.x+p0.y)+(p0.z+p0.w);
        sum1 += (p1.x+p1.y)+(p1.z+p1.w);
        sd0 = fmaf(p0.x,d0.x,sd0); sd0 = fmaf(p0.y,d0.y,sd0); sd0 = fmaf(p0.z,d0.z,sd0); sd0 = fmaf(p0.w,d0.w,sd0);
        sd1 = fmaf(p1.x,d1.x,sd1); sd1 = fmaf(p1.y,d1.y,sd1); sd1 = fmaf(p1.z,d1.z,sd1); sd1 = fmaf(p1.w,d1.w,sd1);
        *(float4*)(sp0 + j0) = p0;
        *(float4*)(sp1 + j0) = p1;
    }
    sum0 = warpSum(sum0); sum1 = warpSum(sum1);
    sd0  = warpSum(sd0);  sd1  = warpSum(sd1);
    float inv0 = 1.f/sum0, inv1 = 1.f/sum1;
    __syncwarp();

    // ---- PV ----
    const float* Vp = v + bh*SN*HD;
    const float4* p0v = (const float4*)sp0;
    const float4* p1v = (const float4*)sp1;
    float a00=0.f,a01=0.f,a02=0.f,a03=0.f;
    float a10=0.f,a11=0.f,a12=0.f,a13=0.f;
    #pragma unroll 4
    for(int j4=0;j4<128;j4++){
        float4 p0 = p0v[j4];
        float4 p1 = p1v[j4];
        const float* vb = Vp + j4*128 + lane;
        float v0 = vb[0], v1 = vb[32], v2 = vb[64], v3 = vb[96];
        a00 = fmaf(p0.x,v0,a00); a01 = fmaf(p0.y,v1,a01);
        a02 = fmaf(p0.z,v2,a02); a03 = fmaf(p0.w,v3,a03);
        a10 = fmaf(p1.x,v0,a10); a11 = fmaf(p1.y,v1,a11);
        a12 = fmaf(p1.z,v2,a12); a13 = fmaf(p1.w,v3,a13);
    }
    float a0 = (a00+a01)+(a02+a03);
    float a1 = (a10+a11)+(a12+a13);
    float wl = We[h*32 + lane], bl = be[h*32 + lane];
    out[((b*SN + i0)*NH + h)*HD + lane] = tfround(a0*inv0 + (sd0*inv0)*wl + bl);
    out[((b*SN + i1)*NH + h)*HD + lane] = tfround(a1*inv1 + (sd1*inv1)*wl + bl);
}

// ---------------- gate + residual, fused next-LN (l=0) or fused decode (l=1) ----------------
template<bool LAST>
__global__ void __launch_bounds__(256) k_gate(const float* __restrict__ o, const float* __restrict__ wg,
                                              float* __restrict__ nodes,
                                              const float* __restrict__ lng, const float* __restrict__ lnb,
                                              float* __restrict__ h,
                                              const float* __restrict__ Wd, float* __restrict__ out){
    int w = threadIdx.x >> 5, lane = threadIdx.x & 31;
    int tok = blockIdx.x*8 + w;
    const float* op = o + tok*DIM;
    float* np = nodes + tok*DIM;
    float ov[8], nv[8];
    float s = 0.f;
    #pragma unroll
    for(int k=0;k<8;k++){
        int c = lane + k*32;
        ov[k] = op[c]; nv[k] = np[c];
        s = fmaf(ov[k], wg[c] + wg[512+c], s);
        s = fmaf(nv[k], wg[256+c] - wg[512+c], s);
    }
    s = warpSum(s);
    float g = 1.f / (1.f + __expf(-s));
    float newv[8];
    float vs = 0.f;
    #pragma unroll
    for(int k=0;k<8;k++){
        newv[k] = ov[k]*g + nv[k]*(1.f - g);
        vs += newv[k];
    }
    if(!LAST){
        vs = warpSum(vs);
        float mean = vs * (1.f/DIM);
        float v2 = 0.f;
        #pragma unroll
        for(int k=0;k<8;k++){ float d = newv[k]-mean; v2 = fmaf(d,d,v2); }
        v2 = warpSum(v2);
        float rstd = rsqrtf(v2*(1.f/DIM) + 1e-5f);
        #pragma unroll
        for(int k=0;k<8;k++){
            int c = lane + k*32;
            np[c] = newv[k];
            h[tok*DIM + c] = tfround(fmaf((newv[k]-mean)*rstd, lng[c], lnb[c]));
        }
    } else {
        float a0 = 0.f, a1 = 0.f, a2 = 0.f;
        #pragma unroll
        for(int k=0;k<8;k++){
            int c = lane + k*32;
            a0 = fmaf(newv[k], Wd[c*3+0], a0);
            a1 = fmaf(newv[k], Wd[c*3+1], a1);
            a2 = fmaf(newv[k], Wd[c*3+2], a2);
        }
        a0 = warpSum(a0); a1 = warpSum(a1); a2 = warpSum(a2);
        if(lane == 0){
            out[tok*3+0] = a0; out[tok*3+1] = a1; out[tok*3+2] = a2;
        }
    }
}

// ---------------- launch ----------------
extern "C" void kernel_launch(void* const* d_in, const int* in_sizes, int n_in,
                              void* d_out, int out_size){
    (void)in_sizes; (void)n_in; (void)out_size;
    const float* x     = (const float*)d_in[0];
    const float* t     = (const float*)d_in[1];
    const float* W_enc = (const float*)d_in[2];
    const float* W_dec = (const float*)d_in[3];
    const float* ln_g  = (const float*)d_in[4];
    const float* ln_b  = (const float*)d_in[5];
    const float* Wq    = (const float*)d_in[6];
    const float* bq    = (const float*)d_in[7];
    const float* Wkv   = (const float*)d_in[8];
    const float* bkv   = (const float*)d_in[9];
    const float* We    = (const float*)d_in[10];
    const float* be    = (const float*)d_in[11];
    const float* Wo    = (const float*)d_in[12];
    const float* bo    = (const float*)d_in[13];
    const float* Wg    = (const float*)d_in[14];
    float* out = (float*)d_out;

    float *dist,*nodes,*h,*q,*kt,*v,*qwe,*qbe,*attno,*ofull,*tab,*wq,*wkv,*wo;
    cudaGetSymbolAddress((void**)&dist,  g_dist);
    cudaGetSymbolAddress((void**)&nodes, g_nodes);
    cudaGetSymbolAddress((void**)&h,     g_h);
    cudaGetSymbolAddress((void**)&q,     g_q);
    cudaGetSymbolAddress((void**)&kt,    g_kt);
    cudaGetSymbolAddress((void**)&v,     g_v);
    cudaGetSymbolAddress((void**)&qwe,   g_qwe);
    cudaGetSymbolAddress((void**)&qbe,   g_qbe);
    cudaGetSymbolAddress((void**)&attno, g_attno);
    cudaGetSymbolAddress((void**)&ofull, g_out);
    cudaGetSymbolAddress((void**)&tab,   g_tab);
    cudaGetSymbolAddress((void**)&wq,    g_wq);
    cudaGetSymbolAddress((void**)&wkv,   g_wkv);
    cudaGetSymbolAddress((void**)&wo,    g_wo);

    const int gemm_smem = 3*(64*36 + 32*72)*4;   // 55296 bytes
    cudaFuncSetAttribute(k_gemm_tc<true>,  cudaFuncAttributeMaxDynamicSharedMemorySize, gemm_smem);
    cudaFuncSetAttribute(k_gemm_tc<false>, cudaFuncAttributeMaxDynamicSharedMemorySize, gemm_smem);

    // side stream: prep (needed by first GEMM) then dist (needed by first attn)
    cudaStream_t sB;
    cudaStreamCreateWithFlags(&sB, cudaStreamNonBlocking);
    cudaEvent_t eF, eP, eJ;
    cudaEventCreateWithFlags(&eF, cudaEventDisableTiming);
    cudaEventCreateWithFlags(&eP, cudaEventDisableTiming);
    cudaEventCreateWithFlags(&eJ, cudaEventDisableTiming);
    cudaEventRecord(eF, 0);
    cudaStreamWaitEvent(sB, eF, 0);
    k_prep<<<2080,256,0,sB>>>(Wq, Wkv, Wo, wq, wkv, wo, tab);
    cudaEventRecord(eP, sB);
    k_dist<<<2048,256,0,sB>>>(x, dist);
    cudaEventRecord(eJ, sB);

    k_encode<<<128,256>>>(x, t, W_enc, ln_g, ln_b, nodes, h);
    cudaStreamWaitEvent(0, eP, 0);

    for(int l=0;l<2;l++){
        k_gemm_tc<true><<<dim3(12,16),256,gemm_smem>>>(h,
            wq + l*DIM*DIM, bq + l*DIM, wkv + l*DIM*2*DIM, bkv + l*2*DIM,
            We + l*DIM, be + l*DIM, tab, q, qwe, qbe, kt, v, nullptr);
        if(l == 0) cudaStreamWaitEvent(0, eJ, 0);
        k_attn2<<<512,256>>>(q, kt, v, qwe, qbe, dist, We + l*DIM, be + l*DIM, attno);
        k_gemm_tc<false><<<dim3(4,16),256,gemm_smem>>>(attno,
            wo + l*DIM*DIM, bo + l*DIM, nullptr, nullptr,
            nullptr, nullptr, nullptr, nullptr, nullptr, nullptr, nullptr, nullptr, ofull);
        if(l == 0)
            k_gate<false><<<128,256>>>(ofull, Wg, nodes, ln_g + DIM, ln_b + DIM, h,
                                       nullptr, nullptr);
        else
            k_gate<true><<<128,256>>>(ofull, Wg + 3*DIM, nodes, nullptr, nullptr, nullptr,
                                      W_dec, out);
    }
}

// round 15
// speedup vs baseline: 1.1580x; 1.0307x over previous
#include <cuda_runtime.h>
#include <math.h>

#define NB 2
#define SN 512
#define DIM 256
#define NH 8
#define HD 32
#define QSCALE 0.17677669529663689f   // 1/sqrt(32)
#define FREQC  0.5756462732485115f    // ln(10000)/16
#define SPST 520                      // sim smem row stride (pad 8)

// ---------------- scratch (device globals) ----------------
__device__ __align__(256) float g_dist [NB*SN*SN];
__device__ __align__(256) float g_nodes[NB*SN*DIM];
__device__ __align__(256) float g_h    [NB*SN*DIM];
__device__ __align__(256) float g_q    [NB*NH*SN*HD];
__device__ __align__(256) float g_kt   [NB*NH*HD*SN];
__device__ __align__(256) float g_v    [NB*NH*SN*HD];
__device__ __align__(256) float g_qwe  [NB*NH*SN];
__device__ __align__(256) float g_qbe  [NB*NH*SN];
__device__ __align__(256) float g_attno[NB*SN*DIM];
__device__ __align__(256) float g_tab  [SN*32];
__device__ __align__(256) float g_wq   [2*DIM*DIM];
__device__ __align__(256) float g_wkv  [2*DIM*2*DIM];
__device__ __align__(256) float g_wo   [2*DIM*DIM];

// ---------------- helpers ----------------
__device__ __forceinline__ float warpSum(float v){
    #pragma unroll
    for(int o=16;o;o>>=1) v += __shfl_xor_sync(0xffffffffu, v, o);
    return v;
}
__device__ __forceinline__ float warpMax(float v){
    #pragma unroll
    for(int o=16;o;o>>=1) v = fmaxf(v, __shfl_xor_sync(0xffffffffu, v, o));
    return v;
}
__device__ __forceinline__ unsigned f2tf(float f){
    unsigned r; asm("cvt.rna.tf32.f32 %0, %1;" : "=r"(r) : "f"(f)); return r;
}
__device__ __forceinline__ float tfround(float f){ return __uint_as_float(f2tf(f)); }
__device__ __forceinline__ void mma8(float* c, unsigned a0, unsigned a1, unsigned a2, unsigned a3,
                                     unsigned b0, unsigned b1){
    asm("mma.sync.aligned.m16n8k8.row.col.f32.tf32.tf32.f32 "
        "{%0,%1,%2,%3},{%4,%5,%6,%7},{%8,%9},{%0,%1,%2,%3};"
        : "+f"(c[0]),"+f"(c[1]),"+f"(c[2]),"+f"(c[3])
        : "r"(a0),"r"(a1),"r"(a2),"r"(a3),"r"(b0),"r"(b1));
}
__device__ __forceinline__ void cpa16(unsigned s, const void* g){
    asm volatile("cp.async.cg.shared.global [%0], [%1], 16;" :: "r"(s), "l"(g));
}

// ---------------- prep: trig table + weight tf32-rounding ----------------
__global__ void __launch_bounds__(256) k_prep(const float* __restrict__ Wq, const float* __restrict__ Wkv,
                                              const float* __restrict__ Wo,
                                              float* __restrict__ wq, float* __restrict__ wkv,
                                              float* __restrict__ wo, float* __restrict__ tab){
    int i = blockIdx.x*256 + threadIdx.x;
    if(i < 8192){
        int ii = i >> 4, fd = i & 15;
        float fr = (float)ii * expf(-(float)fd * FREQC);
        tab[ii*32 + fd]      = cosf(fr);
        tab[ii*32 + 16 + fd] = sinf(fr);
    }
    int j = i - 8192;
    if(j >= 0){
        if(j < 131072)       wq[j]         = tfround(Wq[j]);
        else if(j < 393216)  wkv[j-131072] = tfround(Wkv[j-131072]);
        else if(j < 524288)  wo[j-393216]  = tfround(Wo[j-393216]);
    }
}

// ---------------- pairwise distances ----------------
__global__ void __launch_bounds__(256) k_dist(const float* __restrict__ x, float* __restrict__ dist){
    int idx = blockIdx.x*256 + threadIdx.x;
    int j = idx & 511; int rest = idx >> 9;
    int i = rest & 511; int b = rest >> 9;
    const float* xi = x + (b*SN + i)*3;
    const float* xj = x + (b*SN + j)*3;
    float d0 = xi[0]-xj[0], d1 = xi[1]-xj[1], d2 = xi[2]-xj[2];
    float q = d0*d0 + d1*d1 + d2*d2;
    dist[idx] = (q > 0.f) ? sqrtf(q) : 0.f;
}

// ---------------- encoder + fused LN (warp per token) ----------------
__global__ void __launch_bounds__(256) k_encode(const float* __restrict__ x, const float* __restrict__ t,
                                                const float* __restrict__ W,
                                                const float* __restrict__ lng, const float* __restrict__ lnb,
                                                float* __restrict__ nodes, float* __restrict__ h){
    int w = threadIdx.x >> 5, lane = threadIdx.x & 31;
    int tok = blockIdx.x*8 + w;
    const float* xp = x + tok*3;
    float x0 = xp[0], x1 = xp[1], x2 = xp[2], tt = t[tok];
    float v[8]; float s = 0.f;
    #pragma unroll
    for(int k=0;k<8;k++){
        int c = lane + k*32;
        v[k] = x0*W[c] + x1*W[256+c] + x2*W[512+c] + tt*W[768+c];
        s += v[k];
    }
    s = warpSum(s);
    float mean = s * (1.f/DIM);
    float v2 = 0.f;
    #pragma unroll
    for(int k=0;k<8;k++){ float d = v[k]-mean; v2 = fmaf(d,d,v2); }
    v2 = warpSum(v2);
    float rstd = rsqrtf(v2*(1.f/DIM) + 1e-5f);
    #pragma unroll
    for(int k=0;k<8;k++){
        int c = lane + k*32;
        int idx = tok*DIM + c;
        nodes[idx] = v[k];
        h[idx] = tfround(fmaf((v[k]-mean)*rstd, lng[c], lnb[c]));
    }
}

// ============ tf32 QKV GEMM: BM=64, BN=64, BK=32, NST=3, rotary epilogue ============
__global__ void __launch_bounds__(256) k_qkv_tc(const float* __restrict__ A,
        const float* __restrict__ W1, const float* __restrict__ b1,
        const float* __restrict__ W2, const float* __restrict__ b2,
        const float* __restrict__ We, const float* __restrict__ be,
        const float* __restrict__ tab,
        float* __restrict__ q, float* __restrict__ qwe, float* __restrict__ qbe,
        float* __restrict__ kt, float* __restrict__ v){
    constexpr int BM=64, BK=32, BN=64, K=256, NST=3;
    constexpr int AST = BK+4;
    constexpr int BSTR = BN+8;
    constexpr int ASZ = BM*AST;
    constexpr int BSZ = BK*BSTR;
    extern __shared__ float sm[];
    float* Asm = sm;
    float* Bsm = sm + NST*ASZ;

    int tx = threadIdx.x;
    int wid = tx>>5, lane = tx&31;
    int bcol = blockIdx.x*BN, brow = blockIdx.y*BM;

    const float* W; const float* bias; int ldb;
    if(bcol < 256){ W = W1 + bcol;        bias = b1 + bcol;        ldb = 256; }
    else          { W = W2 + (bcol-256);  bias = b2 + (bcol-256);  ldb = 512; }

    int ar[2], ak4[2];
    #pragma unroll
    for(int u=0;u<2;u++){ int f = tx + u*256; ar[u]=f>>3; ak4[u]=(f&7)*4; }
    int br[2], bc4[2];
    #pragma unroll
    for(int u=0;u<2;u++){ int f = tx + u*256; br[u]=f>>4; bc4[u]=(f&15)*4; }

    const float* Ab = A + brow*K;
    unsigned sA = (unsigned)__cvta_generic_to_shared(Asm);
    unsigned sB = (unsigned)__cvta_generic_to_shared(Bsm);
    unsigned saoff[2], sboff[2];
    #pragma unroll
    for(int u=0;u<2;u++) saoff[u] = (ar[u]*AST + ak4[u])*4u;
    #pragma unroll
    for(int u=0;u<2;u++) sboff[u] = (br[u]*BSTR + bc4[u])*4u;
    const float* ga[2]; const float* gb[2];
    #pragma unroll
    for(int u=0;u<2;u++) ga[u] = Ab + ar[u]*K + ak4[u];
    #pragma unroll
    for(int u=0;u<2;u++) gb[u] = W + br[u]*ldb + bc4[u];

    const int NT = K/BK;   // 8
    #pragma unroll
    for(int s=0;s<2;s++){
        unsigned a0 = sA + s*ASZ*4u, b0 = sB + s*BSZ*4u;
        #pragma unroll
        for(int u=0;u<2;u++) cpa16(a0 + saoff[u], ga[u] + s*BK);
        #pragma unroll
        for(int u=0;u<2;u++) cpa16(b0 + sboff[u], gb[u] + s*BK*ldb);
        asm volatile("cp.async.commit_group;" ::: "memory");
    }

    int wm = (wid & 3)*16, wn = (wid >> 2)*32;
    float acc[4][4];
    #pragma unroll
    for(int nt=0;nt<4;nt++)
        #pragma unroll
        for(int e=0;e<4;e++) acc[nt][e] = 0.f;

    for(int t=0;t<NT;t++){
        asm volatile("cp.async.wait_group 1;" ::: "memory");
        __syncthreads();
        int lt = t+2;
        if(lt < NT){
            int slot = lt % NST;
            unsigned a0 = sA + slot*ASZ*4u, b0 = sB + slot*BSZ*4u;
            #pragma unroll
            for(int u=0;u<2;u++) cpa16(a0 + saoff[u], ga[u] + lt*BK);
            #pragma unroll
            for(int u=0;u<2;u++) cpa16(b0 + sboff[u], gb[u] + lt*BK*ldb);
        }
        asm volatile("cp.async.commit_group;" ::: "memory");

        const float* As_ = Asm + (t%NST)*ASZ;
        const float* Bs_ = Bsm + (t%NST)*BSZ;
        #pragma unroll
        for(int ks=0;ks<4;ks++){
            int kq = ks*8 + (lane&3);
            int arow = wm + (lane>>2);
            unsigned a0 = __float_as_uint(As_[ arow   *AST + kq  ]);
            unsigned a1 = __float_as_uint(As_[(arow+8)*AST + kq  ]);
            unsigned a2 = __float_as_uint(As_[ arow   *AST + kq+4]);
            unsigned a3 = __float_as_uint(As_[(arow+8)*AST + kq+4]);
            int bc0 = wn + (lane>>2);
            unsigned b[4][2];
            #pragma unroll
            for(int nt=0;nt<4;nt++){
                b[nt][0] = __float_as_uint(Bs_[ kq   *BSTR + bc0 + nt*8]);
                b[nt][1] = __float_as_uint(Bs_[(kq+4)*BSTR + bc0 + nt*8]);
            }
            #pragma unroll
            for(int nt=0;nt<4;nt++)
                mma8(acc[nt], a0,a1,a2,a3, b[nt][0],b[nt][1]);
        }
    }

    // epilogue with rotary
    float vv[4][4];
    #pragma unroll
    for(int nt=0;nt<4;nt++){
        int lc = wn + nt*8 + (lane&3)*2;
        float bz0 = bias[lc], bz1 = bias[lc+1];
        vv[nt][0] = acc[nt][0] + bz0;  vv[nt][1] = acc[nt][1] + bz1;
        vv[nt][2] = acc[nt][2] + bz0;  vv[nt][3] = acc[nt][3] + bz1;
    }

    int btype = (bcol < 256) ? 0 : (bcol < 512 ? 1 : 2);
    int hloc;
    if(btype == 0)      hloc = (bcol + wn) >> 5;
    else if(btype == 1) hloc = (bcol - 256 + wn) >> 5;
    else                hloc = (bcol - 512 + wn) >> 5;

    #pragma unroll
    for(int rr=0;rr<2;rr++){
        int tokg = brow + wm + (lane>>2) + rr*8;
        int b = tokg >> 9, i = tokg & 511;
        int bh = b*NH + hloc;

        if(btype == 2){
            float* vd = v + (bh*SN + i)*HD;
            #pragma unroll
            for(int nt=0;nt<4;nt++){
                int d = nt*8 + (lane&3)*2;
                *(float2*)(vd + d) = make_float2(vv[nt][rr*2], vv[nt][rr*2+1]);
            }
        } else {
            float dwe = 0.f, dbe = 0.f;
            #pragma unroll
            for(int nt=0;nt<4;nt++){
                int d0 = nt*8 + (lane&3)*2;
                float rv[2];
                #pragma unroll
                for(int e1=0;e1<2;e1++){
                    int d = d0 + e1, fd = d & 15;
                    float cs = tab[i*32 + fd];
                    float sn = tab[i*32 + 16 + fd];
                    float xv = vv[nt][rr*2+e1];
                    float xp = vv[nt^2][rr*2+e1];
                    float rot = (nt < 2) ? -xp : xp;
                    rv[e1] = xv*cs + rot*sn;
                }
                if(btype == 0){
                    rv[0] = tfround(rv[0]*QSCALE); rv[1] = tfround(rv[1]*QSCALE);
                    dwe = fmaf(rv[0], We[hloc*32 + d0    ], dwe);
                    dwe = fmaf(rv[1], We[hloc*32 + d0 + 1], dwe);
                    dbe = fmaf(rv[0], be[hloc*32 + d0    ], dbe);
                    dbe = fmaf(rv[1], be[hloc*32 + d0 + 1], dbe);
                    *(float2*)(q + (bh*SN + i)*HD + d0) = make_float2(rv[0], rv[1]);
                } else {
                    kt[(bh*HD + d0    )*SN + i] = tfround(rv[0]);
                    kt[(bh*HD + d0 + 1)*SN + i] = tfround(rv[1]);
                }
            }
            if(btype == 0){
                dwe += __shfl_xor_sync(0xffffffffu, dwe, 1);
                dwe += __shfl_xor_sync(0xffffffffu, dwe, 2);
                dbe += __shfl_xor_sync(0xffffffffu, dbe, 1);
                dbe += __shfl_xor_sync(0xffffffffu, dbe, 2);
                if((lane & 3) == 0){
                    qwe[bh*SN + i] = dwe;
                    qbe[bh*SN + i] = dbe;
                }
            }
        }
    }
}

// ============ fused O-projection GEMM + gate (+LN or +decode): BM=16, BN=256 ============
template<bool LAST>
__global__ void __launch_bounds__(256) k_ogate(const float* __restrict__ A,
        const float* __restrict__ W, const float* __restrict__ bias,
        const float* __restrict__ wg, float* __restrict__ nodes,
        const float* __restrict__ lng, const float* __restrict__ lnb, float* __restrict__ h,
        const float* __restrict__ Wd, float* __restrict__ out){
    constexpr int BM=16, BK=32, BN=256, K=256, NST=3;
    constexpr int AST = BK+4;       // 36
    constexpr int BSTR = BN+8;      // 264
    constexpr int ASZ = BM*AST;     // 576
    constexpr int BSZ = BK*BSTR;    // 8448
    extern __shared__ float sm[];
    float* Asm = sm;
    float* Bsm = sm + NST*ASZ;

    int tx = threadIdx.x;
    int wid = tx>>5, lane = tx&31;
    int brow = blockIdx.x*BM;

    int ar = tx>>3, ak4 = (tx&7)*4;
    int br[8], bc4[8];
    #pragma unroll
    for(int u=0;u<8;u++){ int f = tx + u*256; br[u]=f>>6; bc4[u]=(f&63)*4; }

    const float* Ab = A + brow*K;
    unsigned sA = (unsigned)__cvta_generic_to_shared(Asm);
    unsigned sB = (unsigned)__cvta_generic_to_shared(Bsm);
    unsigned saoff = (ar*AST + ak4)*4u;
    unsigned sboff[8];
    #pragma unroll
    for(int u=0;u<8;u++) sboff[u] = (br[u]*BSTR + bc4[u])*4u;
    const float* ga = Ab + ar*K + ak4;
    const float* gb[8];
    #pragma unroll
    for(int u=0;u<8;u++) gb[u] = W + br[u]*256 + bc4[u];

    const int NT = K/BK;   // 8
    #pragma unroll
    for(int s=0;s<2;s++){
        unsigned a0 = sA + s*ASZ*4u, b0 = sB + s*BSZ*4u;
        if(tx < 128) cpa16(a0 + saoff, ga + s*BK);
        #pragma unroll
        for(int u=0;u<8;u++) cpa16(b0 + sboff[u], gb[u] + s*BK*256);
        asm volatile("cp.async.commit_group;" ::: "memory");
    }

    int wn = wid*32;
    float acc[4][4];
    #pragma unroll
    for(int nt=0;nt<4;nt++)
        #pragma unroll
        for(int e=0;e<4;e++) acc[nt][e] = 0.f;

    for(int t=0;t<NT;t++){
        asm volatile("cp.async.wait_group 1;" ::: "memory");
        __syncthreads();
        int lt = t+2;
        if(lt < NT){
            int slot = lt % NST;
            unsigned a0 = sA + slot*ASZ*4u, b0 = sB + slot*BSZ*4u;
            if(tx < 128) cpa16(a0 + saoff, ga + lt*BK);
            #pragma unroll
            for(int u=0;u<8;u++) cpa16(b0 + sboff[u], gb[u] + lt*BK*256);
        }
        asm volatile("cp.async.commit_group;" ::: "memory");

        const float* As_ = Asm + (t%NST)*ASZ;
        const float* Bs_ = Bsm + (t%NST)*BSZ;
        #pragma unroll
        for(int ks=0;ks<4;ks++){
            int kq = ks*8 + (lane&3);
            int arow = lane>>2;
            unsigned a0 = __float_as_uint(As_[ arow   *AST + kq  ]);
            unsigned a1 = __float_as_uint(As_[(arow+8)*AST + kq  ]);
            unsigned a2 = __float_as_uint(As_[ arow   *AST + kq+4]);
            unsigned a3 = __float_as_uint(As_[(arow+8)*AST + kq+4]);
            int bc0 = wn + (lane>>2);
            unsigned b[4][2];
            #pragma unroll
            for(int nt=0;nt<4;nt++){
                b[nt][0] = __float_as_uint(Bs_[ kq   *BSTR + bc0 + nt*8]);
                b[nt][1] = __float_as_uint(Bs_[(kq+4)*BSTR + bc0 + nt*8]);
            }
            #pragma unroll
            for(int nt=0;nt<4;nt++)
                mma8(acc[nt], a0,a1,a2,a3, b[nt][0],b[nt][1]);
        }
    }

    // drain pending (empty) cp.async groups, then reuse smem for C staging
    asm volatile("cp.async.wait_group 0;" ::: "memory");
    __syncthreads();
    float* Csm = sm;
    {
        int rql = lane>>2;
        #pragma unroll
        for(int nt=0;nt<4;nt++){
            int c = wn + nt*8 + (lane&3)*2;
            float bz0 = bias[c], bz1 = bias[c+1];
            Csm[ rql   *BSTR + c  ] = acc[nt][0] + bz0;
            Csm[ rql   *BSTR + c+1] = acc[nt][1] + bz1;
            Csm[(rql+8)*BSTR + c  ] = acc[nt][2] + bz0;
            Csm[(rql+8)*BSTR + c+1] = acc[nt][3] + bz1;
        }
    }
    __syncthreads();

    // gate phase: warp w handles tokens w*2 and w*2+1
    #pragma unroll
    for(int tt=0;tt<2;tt++){
        int tl = wid*2 + tt;
        int tok = brow + tl;
        const float* op = Csm + tl*BSTR;
        float* np = nodes + tok*DIM;
        float ov[8], nv[8];
        float s = 0.f;
        #pragma unroll
        for(int k=0;k<8;k++){
            int c = lane + k*32;
            ov[k] = op[c]; nv[k] = np[c];
            s = fmaf(ov[k], wg[c] + wg[512+c], s);
            s = fmaf(nv[k], wg[256+c] - wg[512+c], s);
        }
        s = warpSum(s);
        float g = 1.f / (1.f + __expf(-s));
        float newv[8];
        float vs = 0.f;
        #pragma unroll
        for(int k=0;k<8;k++){
            newv[k] = ov[k]*g + nv[k]*(1.f - g);
            vs += newv[k];
        }
        if(!LAST){
            vs = warpSum(vs);
            float mean = vs * (1.f/DIM);
            float v2 = 0.f;
            #pragma unroll
            for(int k=0;k<8;k++){ float d = newv[k]-mean; v2 = fmaf(d,d,v2); }
            v2 = warpSum(v2);
            float rstd = rsqrtf(v2*(1.f/DIM) + 1e-5f);
            #pragma unroll
            for(int k=0;k<8;k++){
                int c = lane + k*32;
                np[c] = newv[k];
                h[tok*DIM + c] = tfround(fmaf((newv[k]-mean)*rstd, lng[c], lnb[c]));
            }
        } else {
            float a0 = 0.f, a1 = 0.f, a2 = 0.f;
            #pragma unroll
            for(int k=0;k<8;k++){
                int c = lane + k*32;
                a0 = fmaf(newv[k], Wd[c*3+0], a0);
                a1 = fmaf(newv[k], Wd[c*3+1], a1);
                a2 = fmaf(newv[k], Wd[c*3+2], a2);
            }
            a0 = warpSum(a0); a1 = warpSum(a1); a2 = warpSum(a2);
            if(lane == 0){
                out[tok*3+0] = a0; out[tok*3+1] = a1; out[tok*3+2] = a2;
            }
        }
    }
}

// ---------------- attention: mma QK^T (block 16 rows), fp32 softmax + PV ----------------
__global__ void __launch_bounds__(256) k_attn2(
    const float* __restrict__ q, const float* __restrict__ kt, const float* __restrict__ v,
    const float* __restrict__ qwe, const float* __restrict__ qbe, const float* __restrict__ dist,
    const float* __restrict__ We, const float* __restrict__ be, float* __restrict__ out)
{
    __shared__ __align__(16) float sp[16][SPST];
    int w = threadIdx.x >> 5, lane = threadIdx.x & 31;
    int bh = blockIdx.x >> 5;
    int chunk = blockIdx.x & 31;
    int b = bh >> 3, h = bh & 7;
    int i0base = chunk*16;

    {
        int rql = lane >> 2;
        const float* Q = q + (bh*SN + i0base)*HD;
        unsigned a[4][4];
        #pragma unroll
        for(int kc=0;kc<4;kc++){
            int kq = kc*8 + (lane&3);
            a[kc][0] = __float_as_uint(Q[ rql   *HD + kq  ]);
            a[kc][1] = __float_as_uint(Q[(rql+8)*HD + kq  ]);
            a[kc][2] = __float_as_uint(Q[ rql   *HD + kq+4]);
            a[kc][3] = __float_as_uint(Q[(rql+8)*HD + kq+4]);
        }
        float acc[8][4];
        #pragma unroll
        for(int nt=0;nt<8;nt++){ acc[nt][0]=0.f; acc[nt][1]=0.f; acc[nt][2]=0.f; acc[nt][3]=0.f; }
        const float* Kt = kt + bh*HD*SN;
        int wn2 = w*64;
        #pragma unroll
        for(int kc=0;kc<4;kc++){
            int kq = kc*8 + (lane&3);
            const float* k0 = Kt + kq*SN;
            const float* k4 = Kt + (kq+4)*SN;
            #pragma unroll
            for(int nt=0;nt<8;nt++){
                int j = wn2 + nt*8 + rql;
                mma8(acc[nt], a[kc][0],a[kc][1],a[kc][2],a[kc][3],
                     __float_as_uint(k0[j]), __float_as_uint(k4[j]));
            }
        }
        int r0 = i0base + rql, r1 = r0 + 8;
        float cwe0 = qwe[bh*SN + r0], cbe0 = qbe[bh*SN + r0];
        float cwe1 = qwe[bh*SN + r1], cbe1 = qbe[bh*SN + r1];
        const float* Dr0 = dist + (b*SN + r0)*SN;
        const float* Dr1 = dist + (b*SN + r1)*SN;
        #pragma unroll
        for(int nt=0;nt<8;nt++){
            int c = wn2 + nt*8 + (lane&3)*2;
            float2 dd0 = *(const float2*)(Dr0 + c);
            float2 dd1 = *(const float2*)(Dr1 + c);
            sp[rql  ][c  ] = fmaf(dd0.x, cwe0, acc[nt][0] + cbe0);
            sp[rql  ][c+1] = fmaf(dd0.y, cwe0, acc[nt][1] + cbe0);
            sp[rql+8][c  ] = fmaf(dd1.x, cwe1, acc[nt][2] + cbe1);
            sp[rql+8][c+1] = fmaf(dd1.y, cwe1, acc[nt][3] + cbe1);
        }
    }
    __syncthreads();

    int i0 = i0base + w*2, i1 = i0 + 1;
    float* sp0 = sp[w*2];
    float* sp1 = sp[w*2+1];
    const float* D0 = dist + (b*SN + i0)*SN;
    const float* D1 = dist + (b*SN + i1)*SN;

    float m0 = -1e30f, m1 = -1e30f;
    #pragma unroll
    for(int cb=0;cb<4;cb++){
        int j0 = cb*128 + lane*4;
        float4 s0 = *(const float4*)(sp0 + j0);
        float4 s1 = *(const float4*)(sp1 + j0);
        m0 = fmaxf(m0, fmaxf(fmaxf(s0.x,s0.y), fmaxf(s0.z,s0.w)));
        m1 = fmaxf(m1, fmaxf(fmaxf(s1.x,s1.y), fmaxf(s1.z,s1.w)));
    }
    m0 = warpMax(m0); m1 = warpMax(m1);

    float sum0 = 0.f, sum1 = 0.f, sd0 = 0.f, sd1 = 0.f;
    #pragma unroll
    for(int cb=0;cb<4;cb++){
        int j0 = cb*128 + lane*4;
        float4 s0 = *(const float4*)(sp0 + j0);
        float4 s1 = *(const float4*)(sp1 + j0);
        float4 d0 = *(const float4*)(D0 + j0);
        float4 d1 = *(const float4*)(D1 + j0);
        float4 p0, p1;
        p0.x = __expf(s0.x-m0); p0.y = __expf(s0.y-m0); p0.z = __expf(s0.z-m0); p0.w = __expf(s0.w-m0);
        p1.x = __expf(s1.x-m1); p1.y = __expf(s1.y-m1); p1.z = __expf(s1.z-m1); p1.w = __expf(s1.w-m1);
        sum0 += (p0.x+p0.y)+(p0.z+p0.w);
        sum1 += (p1.x+p1.y)+(p1.z+p1.w);
        sd0 = fmaf(p0.x,d0.x,sd0); sd0 = fmaf(p0.y,d0.y,sd0); sd0 = fmaf(p0.z,d0.z,sd0); sd0 = fmaf(p0.w,d0.w,sd0);
        sd1 = fmaf(p1.x,d1.x,sd1); sd1 = fmaf(p1.y,d1.y,sd1); sd1 = fmaf(p1.z,d1.z,sd1); sd1 = fmaf(p1.w,d1.w,sd1);
        *(float4*)(sp0 + j0) = p0;
        *(float4*)(sp1 + j0) = p1;
    }
    sum0 = warpSum(sum0); sum1 = warpSum(sum1);
    sd0  = warpSum(sd0);  sd1  = warpSum(sd1);
    float inv0 = 1.f/sum0, inv1 = 1.f/sum1;
    __syncwarp();

    const float* Vp = v + bh*SN*HD;
    const float4* p0v = (const float4*)sp0;
    const float4* p1v = (const float4*)sp1;
    float a00=0.f,a01=0.f,a02=0.f,a03=0.f;
    float a10=0.f,a11=0.f,a12=0.f,a13=0.f;
    #pragma unroll 4
    for(int j4=0;j4<128;j4++){
        float4 p0 = p0v[j4];
        float4 p1 = p1v[j4];
        const float* vb = Vp + j4*128 + lane;
        float v0 = vb[0], v1 = vb[32], v2 = vb[64], v3 = vb[96];
        a00 = fmaf(p0.x,v0,a00); a01 = fmaf(p0.y,v1,a01);
        a02 = fmaf(p0.z,v2,a02); a03 = fmaf(p0.w,v3,a03);
        a10 = fmaf(p1.x,v0,a10); a11 = fmaf(p1.y,v1,a11);
        a12 = fmaf(p1.z,v2,a12); a13 = fmaf(p1.w,v3,a13);
    }
    float a0 = (a00+a01)+(a02+a03);
    float a1 = (a10+a11)+(a12+a13);
    float wl = We[h*32 + lane], bl = be[h*32 + lane];
    out[((b*SN + i0)*NH + h)*HD + lane] = tfround(a0*inv0 + (sd0*inv0)*wl + bl);
    out[((b*SN + i1)*NH + h)*HD + lane] = tfround(a1*inv1 + (sd1*inv1)*wl + bl);
}

// ---------------- launch ----------------
extern "C" void kernel_launch(void* const* d_in, const int* in_sizes, int n_in,
                              void* d_out, int out_size){
    (void)in_sizes; (void)n_in; (void)out_size;
    const float* x     = (const float*)d_in[0];
    const float* t     = (const float*)d_in[1];
    const float* W_enc = (const float*)d_in[2];
    const float* W_dec = (const float*)d_in[3];
    const float* ln_g  = (const float*)d_in[4];
    const float* ln_b  = (const float*)d_in[5];
    const float* Wq    = (const float*)d_in[6];
    const float* bq    = (const float*)d_in[7];
    const float* Wkv   = (const float*)d_in[8];
    const float* bkv   = (const float*)d_in[9];
    const float* We    = (const float*)d_in[10];
    const float* be    = (const float*)d_in[11];
    const float* Wo    = (const float*)d_in[12];
    const float* bo    = (const float*)d_in[13];
    const float* Wg    = (const float*)d_in[14];
    float* out = (float*)d_out;

    float *dist,*nodes,*h,*q,*kt,*v,*qwe,*qbe,*attno,*tab,*wq,*wkv,*wo;
    cudaGetSymbolAddress((void**)&dist,  g_dist);
    cudaGetSymbolAddress((void**)&nodes, g_nodes);
    cudaGetSymbolAddress((void**)&h,     g_h);
    cudaGetSymbolAddress((void**)&q,     g_q);
    cudaGetSymbolAddress((void**)&kt,    g_kt);
    cudaGetSymbolAddress((void**)&v,     g_v);
    cudaGetSymbolAddress((void**)&qwe,   g_qwe);
    cudaGetSymbolAddress((void**)&qbe,   g_qbe);
    cudaGetSymbolAddress((void**)&attno, g_attno);
    cudaGetSymbolAddress((void**)&tab,   g_tab);
    cudaGetSymbolAddress((void**)&wq,    g_wq);
    cudaGetSymbolAddress((void**)&wkv,   g_wkv);
    cudaGetSymbolAddress((void**)&wo,    g_wo);

    const int qkv_smem = 3*(64*36 + 32*72)*4;      // 55296 bytes
    const int ogate_smem = 3*(16*36 + 32*264)*4;   // 108288 bytes
    cudaFuncSetAttribute(k_qkv_tc, cudaFuncAttributeMaxDynamicSharedMemorySize, qkv_smem);
    cudaFuncSetAttribute(k_ogate<false>, cudaFuncAttributeMaxDynamicSharedMemorySize, ogate_smem);
    cudaFuncSetAttribute(k_ogate<true>,  cudaFuncAttributeMaxDynamicSharedMemorySize, ogate_smem);

    // side stream: prep (needed by first GEMM) then dist (needed by first attn)
    cudaStream_t sB;
    cudaStreamCreateWithFlags(&sB, cudaStreamNonBlocking);
    cudaEvent_t eF, eP, eJ;
    cudaEventCreateWithFlags(&eF, cudaEventDisableTiming);
    cudaEventCreateWithFlags(&eP, cudaEventDisableTiming);
    cudaEventCreateWithFlags(&eJ, cudaEventDisableTiming);
    cudaEventRecord(eF, 0);
    cudaStreamWaitEvent(sB, eF, 0);
    k_prep<<<2080,256,0,sB>>>(Wq, Wkv, Wo, wq, wkv, wo, tab);
    cudaEventRecord(eP, sB);
    k_dist<<<2048,256,0,sB>>>(x, dist);
    cudaEventRecord(eJ, sB);

    k_encode<<<128,256>>>(x, t, W_enc, ln_g, ln_b, nodes, h);
    cudaStreamWaitEvent(0, eP, 0);

    for(int l=0;l<2;l++){
        k_qkv_tc<<<dim3(12,16),256,qkv_smem>>>(h,
            wq + l*DIM*DIM, bq + l*DIM, wkv + l*DIM*2*DIM, bkv + l*2*DIM,
            We + l*DIM, be + l*DIM, tab, q, qwe, qbe, kt, v);
        if(l == 0) cudaStreamWaitEvent(0, eJ, 0);
        k_attn2<<<512,256>>>(q, kt, v, qwe, qbe, dist, We + l*DIM, be + l*DIM, attno);
        if(l == 0)
            k_ogate<false><<<64,256,ogate_smem>>>(attno, wo, bo, Wg, nodes,
                                                  ln_g + DIM, ln_b + DIM, h, nullptr, nullptr);
        else
            k_ogate<true><<<64,256,ogate_smem>>>(attno, wo + DIM*DIM, bo + DIM, Wg + 3*DIM, nodes,
                                                 nullptr, nullptr, nullptr, W_dec, out);
    }
}